// round 1
// baseline (speedup 1.0000x reference)
#include <cuda_runtime.h>
#include <math.h>

// Problem constants
#define B_ 4
#define T_ 1024
#define D_ 1024
#define H_ 16
#define S_ 64
#define HID_ 3072
#define BT_ (B_*T_)

// ---------------- scratch (device globals; no allocation allowed) -----------
__device__ unsigned g_amax[8];
__device__ float g_wqq[D_*D_];
__device__ float g_wkq[D_*D_];
__device__ float g_wvq[D_*D_];
__device__ float g_woq[D_*D_];
__device__ float g_suq[S_*S_];
__device__ float g_svq[S_*S_];
__device__ float g_wqf[D_*D_];      // blockdiag(su_q) @ wq_q
__device__ float g_wkf[D_*D_];      // blockdiag(sv_q) @ wk_q
__device__ float g_wupq[HID_*D_];
__device__ float g_wdnq[D_*HID_];
__device__ float g_xn[BT_*D_];
__device__ float g_q[BT_*D_];
__device__ float g_k[BT_*D_];
__device__ float g_v[BT_*D_];
__device__ float g_att[BT_*D_];
__device__ float g_x1[BT_*D_];
__device__ float g_h[BT_*HID_];
__device__ float g_act[BT_*HID_];

// ---------------- quantization --------------------------------------------
__global__ void k_zero_amax() {
    if (threadIdx.x < 8) g_amax[threadIdx.x] = 0u;
}

__global__ void k_absmax(const float* __restrict__ w, int n, int slot) {
    float m = 0.f;
    for (int i = blockIdx.x * blockDim.x + threadIdx.x; i < n;
         i += gridDim.x * blockDim.x)
        m = fmaxf(m, fabsf(w[i]));
#pragma unroll
    for (int o = 16; o; o >>= 1)
        m = fmaxf(m, __shfl_xor_sync(0xffffffffu, m, o));
    __shared__ float sm[8];
    int wid = threadIdx.x >> 5;
    if ((threadIdx.x & 31) == 0) sm[wid] = m;
    __syncthreads();
    if (threadIdx.x == 0) {
        int nw = blockDim.x >> 5;
        for (int i = 1; i < nw; i++) m = fmaxf(m, sm[i]);
        atomicMax(&g_amax[slot], __float_as_uint(m));
    }
}

__global__ void k_quant(const float* __restrict__ w, float* __restrict__ o,
                        int n, int slot) {
    float amax = __uint_as_float(g_amax[slot]);
    float scale = amax / 31.0f + 1e-8f;
    for (int i = blockIdx.x * blockDim.x + threadIdx.x; i < n;
         i += gridDim.x * blockDim.x) {
        float q = rintf(w[i] / scale);       // rintf = round-half-even = jnp.round
        q = fminf(fmaxf(q, -31.f), 31.f);
        o[i] = q * scale;
    }
}

// ---------------- fold stalk map into projection ---------------------------
// out[h*64+sp, k] = sum_s stalk[sp,s] * w[h*64+s, k]
__global__ void k_fold(const float* __restrict__ stalk,
                       const float* __restrict__ w, float* __restrict__ o) {
    int idx = blockIdx.x * 256 + threadIdx.x;     // 0 .. D*D-1
    int r = idx >> 10;                            // output row
    int kk = idx & 1023;
    int hbase = r & ~63;
    int sp = r & 63;
    float acc = 0.f;
#pragma unroll 8
    for (int s = 0; s < 64; s++)
        acc += stalk[sp * 64 + s] * w[(hbase + s) * 1024 + kk];
    o[idx] = acc;
}

// ---------------- layernorm (+ optional silu) ------------------------------
__global__ void k_ln(const float* __restrict__ x, const float* __restrict__ g,
                     const float* __restrict__ bb, float* __restrict__ out,
                     int n, int do_silu) {
    extern __shared__ float row[];
    int r = blockIdx.x;
    int tid = threadIdx.x;
    const float* xr = x + (size_t)r * n;
    float s = 0.f, s2 = 0.f;
    for (int i = tid; i < n; i += blockDim.x) {
        float v = xr[i];
        row[i] = v;
        s += v;
        s2 += v * v;
    }
#pragma unroll
    for (int o = 16; o; o >>= 1) {
        s += __shfl_xor_sync(0xffffffffu, s, o);
        s2 += __shfl_xor_sync(0xffffffffu, s2, o);
    }
    __shared__ float rs[8], rs2[8];
    __shared__ float mu_s, inv_s;
    int wid = tid >> 5;
    if ((tid & 31) == 0) { rs[wid] = s; rs2[wid] = s2; }
    __syncthreads();
    if (tid == 0) {
        float S = 0.f, S2 = 0.f;
        int nw = blockDim.x >> 5;
        for (int i = 0; i < nw; i++) { S += rs[i]; S2 += rs2[i]; }
        float mu = S / n;
        float var = S2 / n - mu * mu;
        mu_s = mu;
        inv_s = rsqrtf(var + 1e-5f);
    }
    __syncthreads();
    float mu = mu_s, inv = inv_s;
    float* orow = out + (size_t)r * n;
    for (int i = tid; i < n; i += blockDim.x) {
        float y = (row[i] - mu) * inv * g[i] + bb[i];
        if (do_silu) y = y / (1.0f + __expf(-y));
        orow[i] = y;
    }
}

// ---------------- SGEMM: C[M,N] = A[M,K] * B[N,K]^T  (NT) ------------------
// mode 0: plain    mode 1: C = R + A*B^T    mode 2: SO(2) rotation epilogue
#define BM 128
#define BN 64
#define BK 16

__global__ __launch_bounds__(256)
void k_gemm(const float* __restrict__ A, const float* __restrict__ Bm,
            float* __restrict__ C, const float* __restrict__ R,
            const float* __restrict__ theta, int M, int N, int K, int mode) {
    __shared__ __align__(16) float As[BK][BM + 4];
    __shared__ __align__(16) float Bs[BK][BN + 4];
    int tid = threadIdx.x;
    int tx = tid & 15, ty = tid >> 4;
    int bm = blockIdx.y * BM;
    int bn = blockIdx.x * BN;
    const float* Ab = A + (size_t)bm * K;
    const float* Bb = Bm + (size_t)bn * K;

    float acc[8][4];
#pragma unroll
    for (int i = 0; i < 8; i++)
#pragma unroll
        for (int j = 0; j < 4; j++) acc[i][j] = 0.f;

    for (int kb = 0; kb < K; kb += BK) {
#pragma unroll
        for (int i = 0; i < 2; i++) {
            int idx = tid + i * 256;       // 0..511
            int r = idx >> 2;              // 0..127
            int c4 = idx & 3;              // 0..3
            float4 v = *(const float4*)(Ab + (size_t)r * K + kb + c4 * 4);
            As[c4 * 4 + 0][r] = v.x;
            As[c4 * 4 + 1][r] = v.y;
            As[c4 * 4 + 2][r] = v.z;
            As[c4 * 4 + 3][r] = v.w;
        }
        {
            int r = tid >> 2;              // 0..63
            int c4 = tid & 3;
            float4 v = *(const float4*)(Bb + (size_t)r * K + kb + c4 * 4);
            Bs[c4 * 4 + 0][r] = v.x;
            Bs[c4 * 4 + 1][r] = v.y;
            Bs[c4 * 4 + 2][r] = v.z;
            Bs[c4 * 4 + 3][r] = v.w;
        }
        __syncthreads();
#pragma unroll
        for (int kk = 0; kk < BK; kk++) {
            float4 a0 = *(float4*)&As[kk][ty * 8];
            float4 a1 = *(float4*)&As[kk][ty * 8 + 4];
            float4 bv = *(float4*)&Bs[kk][tx * 4];
            float a[8] = {a0.x, a0.y, a0.z, a0.w, a1.x, a1.y, a1.z, a1.w};
            float bvv[4] = {bv.x, bv.y, bv.z, bv.w};
#pragma unroll
            for (int i = 0; i < 8; i++)
#pragma unroll
                for (int j = 0; j < 4; j++) acc[i][j] += a[i] * bvv[j];
        }
        __syncthreads();
    }

    int col = bn + tx * 4;
#pragma unroll
    for (int i = 0; i < 8; i++) {
        int row = bm + ty * 8 + i;
        float4 o;
        if (mode == 2) {
            float c0 = cosf(theta[col >> 1]), s0 = sinf(theta[col >> 1]);
            float c1 = cosf(theta[(col + 2) >> 1]), s1 = sinf(theta[(col + 2) >> 1]);
            float a0 = acc[i][0], b0 = acc[i][1];
            float a1 = acc[i][2], b1 = acc[i][3];
            o.x = c0 * a0 - s0 * b0;
            o.y = s0 * a0 + c0 * b0;
            o.z = c1 * a1 - s1 * b1;
            o.w = s1 * a1 + c1 * b1;
        } else {
            o.x = acc[i][0]; o.y = acc[i][1]; o.z = acc[i][2]; o.w = acc[i][3];
        }
        if (mode == 1) {
            float4 rv = *(const float4*)(R + (size_t)row * N + col);
            o.x += rv.x; o.y += rv.y; o.z += rv.z; o.w += rv.w;
        }
        *(float4*)(C + (size_t)row * N + col) = o;
    }
}

// ---------------- attention (flash-style, p-adic bias on the fly) ----------
// grid (T/64, H, B); 256 threads; per-thread 4x4 score tile / 4x4 O tile
#define ATTN_SMEM (4 * 64 * 68 * 4)

__global__ __launch_bounds__(256)
void k_attn(const float* __restrict__ Q, const float* __restrict__ K,
            const float* __restrict__ V, float* __restrict__ O,
            const float* __restrict__ p_scale_ptr) {
    extern __shared__ __align__(16) float smp[];
    float* Qt = smp;                    // [s][r]  64x68
    float* Kt = smp + 64 * 68;          // [s][u]
    float* Vs = smp + 2 * 64 * 68;      // [u][c]
    float* Pt = smp + 3 * 64 * 68;      // [u][r]

    int qt = blockIdx.x, h = blockIdx.y, b = blockIdx.z;
    int tid = threadIdx.x;
    int tx = tid & 15, ty = tid >> 4;
    float ps = p_scale_ptr[0];
    const float scale = 0.125f;

    size_t baseQ = ((size_t)(b * T_) + qt * 64) * D_ + h * 64;
#pragma unroll
    for (int i = 0; i < 4; i++) {
        int idx = tid + i * 256;        // 0..1023
        int r = idx >> 4;               // 0..63
        int c4 = idx & 15;              // 0..15
        float4 v = *(const float4*)(Q + baseQ + (size_t)r * D_ + c4 * 4);
        Qt[(c4 * 4 + 0) * 68 + r] = v.x;
        Qt[(c4 * 4 + 1) * 68 + r] = v.y;
        Qt[(c4 * 4 + 2) * 68 + r] = v.z;
        Qt[(c4 * 4 + 3) * 68 + r] = v.w;
    }

    float m_i[4], l_i[4], acc[4][4];
#pragma unroll
    for (int i = 0; i < 4; i++) {
        m_i[i] = -1e30f;
        l_i[i] = 0.f;
#pragma unroll
        for (int j = 0; j < 4; j++) acc[i][j] = 0.f;
    }

    for (int jt = 0; jt <= qt; jt++) {
        __syncthreads();   // protect Kt/Vs/Pt from previous iteration readers
        size_t baseK = ((size_t)(b * T_) + jt * 64) * D_ + h * 64;
#pragma unroll
        for (int i = 0; i < 4; i++) {
            int idx = tid + i * 256;
            int r = idx >> 4;
            int c4 = idx & 15;
            float4 v = *(const float4*)(K + baseK + (size_t)r * D_ + c4 * 4);
            Kt[(c4 * 4 + 0) * 68 + r] = v.x;
            Kt[(c4 * 4 + 1) * 68 + r] = v.y;
            Kt[(c4 * 4 + 2) * 68 + r] = v.z;
            Kt[(c4 * 4 + 3) * 68 + r] = v.w;
            float4 w = *(const float4*)(V + baseK + (size_t)r * D_ + c4 * 4);
            *(float4*)&Vs[r * 68 + c4 * 4] = w;
        }
        __syncthreads();

        float sc[4][4];
#pragma unroll
        for (int i = 0; i < 4; i++)
#pragma unroll
            for (int j = 0; j < 4; j++) sc[i][j] = 0.f;
#pragma unroll 8
        for (int s = 0; s < 64; s++) {
            float4 a = *(float4*)&Qt[s * 68 + ty * 4];
            float4 bv = *(float4*)&Kt[s * 68 + tx * 4];
            float av[4] = {a.x, a.y, a.z, a.w};
            float bvv[4] = {bv.x, bv.y, bv.z, bv.w};
#pragma unroll
            for (int i = 0; i < 4; i++)
#pragma unroll
                for (int j = 0; j < 4; j++) sc[i][j] += av[i] * bvv[j];
        }

        int q0 = qt * 64 + ty * 4;
        int k0 = jt * 64 + tx * 4;
#pragma unroll
        for (int i = 0; i < 4; i++) {
#pragma unroll
            for (int j = 0; j < 4; j++) {
                int d = (q0 + i) - (k0 + j);
                if (d < 0) {
                    sc[i][j] = -1e30f;
                } else {
                    float bias = (d == 0) ? 1.0f
                        : fminf((float)(__ffs(d) - 1), 16.f) * 0.0625f;
                    sc[i][j] = sc[i][j] * scale + ps * bias;
                }
            }
        }

#pragma unroll
        for (int i = 0; i < 4; i++) {
            float rm = fmaxf(fmaxf(sc[i][0], sc[i][1]), fmaxf(sc[i][2], sc[i][3]));
#pragma unroll
            for (int o = 1; o < 16; o <<= 1)
                rm = fmaxf(rm, __shfl_xor_sync(0xffffffffu, rm, o));
            float mnew = fmaxf(m_i[i], rm);
            float alpha = __expf(m_i[i] - mnew);
            m_i[i] = mnew;
            float rsum = 0.f;
#pragma unroll
            for (int j = 0; j < 4; j++) {
                float p = __expf(sc[i][j] - mnew);
                sc[i][j] = p;
                rsum += p;
            }
#pragma unroll
            for (int o = 1; o < 16; o <<= 1)
                rsum += __shfl_xor_sync(0xffffffffu, rsum, o);
            l_i[i] = l_i[i] * alpha + rsum;
#pragma unroll
            for (int j = 0; j < 4; j++) acc[i][j] *= alpha;
        }

        // write P transposed: Pt[key][query-row]
#pragma unroll
        for (int j = 0; j < 4; j++) {
            float4 p4 = make_float4(sc[0][j], sc[1][j], sc[2][j], sc[3][j]);
            *(float4*)&Pt[(tx * 4 + j) * 68 + ty * 4] = p4;
        }
        __syncthreads();

#pragma unroll 8
        for (int u = 0; u < 64; u++) {
            float4 p = *(float4*)&Pt[u * 68 + ty * 4];
            float4 vv = *(float4*)&Vs[u * 68 + tx * 4];
            float pv[4] = {p.x, p.y, p.z, p.w};
            float vvv[4] = {vv.x, vv.y, vv.z, vv.w};
#pragma unroll
            for (int i = 0; i < 4; i++)
#pragma unroll
                for (int j = 0; j < 4; j++) acc[i][j] += pv[i] * vvv[j];
        }
    }

#pragma unroll
    for (int i = 0; i < 4; i++) {
        float inv = 1.0f / l_i[i];
        float4 o = make_float4(acc[i][0] * inv, acc[i][1] * inv,
                               acc[i][2] * inv, acc[i][3] * inv);
        size_t orow = ((size_t)(b * T_) + qt * 64 + ty * 4 + i) * D_ + h * 64 + tx * 4;
        *(float4*)(O + orow) = o;
    }
}

// ---------------- host orchestration ---------------------------------------
extern "C" void kernel_launch(void* const* d_in, const int* in_sizes, int n_in,
                              void* d_out, int out_size) {
    const float* x      = (const float*)d_in[0];
    const float* wq     = (const float*)d_in[1];
    const float* wk     = (const float*)d_in[2];
    const float* wv     = (const float*)d_in[3];
    const float* wo     = (const float*)d_in[4];
    const float* su     = (const float*)d_in[5];
    const float* sv     = (const float*)d_in[6];
    const float* pscale = (const float*)d_in[7];
    const float* n1g    = (const float*)d_in[8];
    const float* n1b    = (const float*)d_in[9];
    const float* n2g    = (const float*)d_in[10];
    const float* n2b    = (const float*)d_in[11];
    const float* w_up   = (const float*)d_in[12];
    const float* w_down = (const float*)d_in[13];
    const float* theta  = (const float*)d_in[14];
    const float* mg     = (const float*)d_in[15];
    const float* mb     = (const float*)d_in[16];
    float* out = (float*)d_out;

    float *wqq, *wkq, *wvq, *woq, *suq, *svq, *wqf, *wkf, *wupq, *wdnq;
    float *xn, *qb, *kb, *vb, *att, *x1, *hb, *act;
    cudaGetSymbolAddress((void**)&wqq, g_wqq);
    cudaGetSymbolAddress((void**)&wkq, g_wkq);
    cudaGetSymbolAddress((void**)&wvq, g_wvq);
    cudaGetSymbolAddress((void**)&woq, g_woq);
    cudaGetSymbolAddress((void**)&suq, g_suq);
    cudaGetSymbolAddress((void**)&svq, g_svq);
    cudaGetSymbolAddress((void**)&wqf, g_wqf);
    cudaGetSymbolAddress((void**)&wkf, g_wkf);
    cudaGetSymbolAddress((void**)&wupq, g_wupq);
    cudaGetSymbolAddress((void**)&wdnq, g_wdnq);
    cudaGetSymbolAddress((void**)&xn, g_xn);
    cudaGetSymbolAddress((void**)&qb, g_q);
    cudaGetSymbolAddress((void**)&kb, g_k);
    cudaGetSymbolAddress((void**)&vb, g_v);
    cudaGetSymbolAddress((void**)&att, g_att);
    cudaGetSymbolAddress((void**)&x1, g_x1);
    cudaGetSymbolAddress((void**)&hb, g_h);
    cudaGetSymbolAddress((void**)&act, g_act);

    cudaFuncSetAttribute(k_attn, cudaFuncAttributeMaxDynamicSharedMemorySize,
                         ATTN_SMEM);

    // ---- quantize weights ----
    k_zero_amax<<<1, 32>>>();
    auto amax_blocks = [](int n) { int b = (n + 255) / 256; return b > 256 ? 256 : b; };
    k_absmax<<<amax_blocks(D_*D_), 256>>>(wq, D_*D_, 0);
    k_absmax<<<amax_blocks(D_*D_), 256>>>(wk, D_*D_, 1);
    k_absmax<<<amax_blocks(D_*D_), 256>>>(wv, D_*D_, 2);
    k_absmax<<<amax_blocks(D_*D_), 256>>>(wo, D_*D_, 3);
    k_absmax<<<amax_blocks(S_*S_), 256>>>(su, S_*S_, 4);
    k_absmax<<<amax_blocks(S_*S_), 256>>>(sv, S_*S_, 5);
    k_absmax<<<amax_blocks(HID_*D_), 256>>>(w_up, HID_*D_, 6);
    k_absmax<<<amax_blocks(HID_*D_), 256>>>(w_down, HID_*D_, 7);
    auto qblocks = [](int n) { int b = (n + 255) / 256; return b > 4096 ? 4096 : b; };
    k_quant<<<qblocks(D_*D_), 256>>>(wq, wqq, D_*D_, 0);
    k_quant<<<qblocks(D_*D_), 256>>>(wk, wkq, D_*D_, 1);
    k_quant<<<qblocks(D_*D_), 256>>>(wv, wvq, D_*D_, 2);
    k_quant<<<qblocks(D_*D_), 256>>>(wo, woq, D_*D_, 3);
    k_quant<<<qblocks(S_*S_), 256>>>(su, suq, S_*S_, 4);
    k_quant<<<qblocks(S_*S_), 256>>>(sv, svq, S_*S_, 5);
    k_quant<<<qblocks(HID_*D_), 256>>>(w_up, wupq, HID_*D_, 6);
    k_quant<<<qblocks(HID_*D_), 256>>>(w_down, wdnq, HID_*D_, 7);

    // ---- fold stalk maps into Q/K projections ----
    k_fold<<<(D_*D_)/256, 256>>>(suq, wqq, wqf);
    k_fold<<<(D_*D_)/256, 256>>>(svq, wkq, wkf);

    // ---- ln1 ----
    k_ln<<<BT_, 256, D_ * 4>>>(x, n1g, n1b, xn, D_, 0);

    // ---- Q/K/V projections (stalk maps pre-folded) ----
    dim3 gq(D_ / BN, BT_ / BM);
    k_gemm<<<gq, 256>>>(xn, wqf, qb, nullptr, nullptr, BT_, D_, D_, 0);
    k_gemm<<<gq, 256>>>(xn, wkf, kb, nullptr, nullptr, BT_, D_, D_, 0);
    k_gemm<<<gq, 256>>>(xn, wvq, vb, nullptr, nullptr, BT_, D_, D_, 0);

    // ---- attention ----
    k_attn<<<dim3(T_ / 64, H_, B_), 256, ATTN_SMEM>>>(qb, kb, vb, att, pscale);

    // ---- output projection + residual ----
    k_gemm<<<gq, 256>>>(att, woq, x1, x, nullptr, BT_, D_, D_, 1);

    // ---- ln2 ----
    k_ln<<<BT_, 256, D_ * 4>>>(x1, n2g, n2b, xn, D_, 0);

    // ---- MLP up + SO(2) rotation epilogue ----
    dim3 gu(HID_ / BN, BT_ / BM);
    k_gemm<<<gu, 256>>>(xn, wupq, hb, nullptr, theta, BT_, HID_, D_, 2);

    // ---- mlp layernorm + silu ----
    k_ln<<<BT_, 256, HID_ * 4>>>(hb, mg, mb, act, HID_, 1);

    // ---- MLP down + residual -> output ----
    k_gemm<<<gq, 256>>>(act, wdnq, out, x1, nullptr, BT_, D_, HID_, 1);
}

// round 4
// speedup vs baseline: 1.9696x; 1.9696x over previous
#include <cuda_runtime.h>
#include <cuda_bf16.h>
#include <math.h>
#include <stdint.h>

// Problem constants
#define B_ 4
#define T_ 1024
#define D_ 1024
#define H_ 16
#define S_ 64
#define HID_ 3072
#define BT_ (B_*T_)
#define KK_D 3072      // 3*D   (hi|hi|lo split K)
#define KK_H 9216      // 3*HID

// ---------------- scratch (device globals; no allocation allowed) -----------
__device__ unsigned g_amax[8];
__device__ float g_wqq[D_*D_];
__device__ float g_wkq[D_*D_];
__device__ float g_wvq[D_*D_];
__device__ float g_woq[D_*D_];
__device__ float g_suq[S_*S_];
__device__ float g_svq[S_*S_];
__device__ float g_wqf[D_*D_];
__device__ float g_wkf[D_*D_];
__device__ float g_wupq[HID_*D_];
__device__ float g_wdnq[D_*HID_];
__device__ float g_qkv[BT_*3*D_];
__device__ float g_att[BT_*D_];
__device__ float g_x1[BT_*D_];
__device__ float g_h[BT_*HID_];
__device__ __nv_bfloat16 g_as[BT_*KK_D];
__device__ __nv_bfloat16 g_acts[(size_t)BT_*KK_H];
__device__ __nv_bfloat16 g_wqkvs[3*D_*KK_D];
__device__ __nv_bfloat16 g_wos[D_*KK_D];
__device__ __nv_bfloat16 g_wups[HID_*KK_D];
__device__ __nv_bfloat16 g_wdns[(size_t)D_*KK_H];

// ---------------- inline PTX helpers ----------------------------------------
__device__ __forceinline__ uint32_t smem_u32(const void* p) {
    uint32_t a;
    asm("{ .reg .u64 t; cvta.to.shared.u64 t, %1; cvt.u32.u64 %0, t; }"
        : "=r"(a) : "l"(p));
    return a;
}
__device__ __forceinline__ void cpa16(uint32_t dst, const void* src) {
    asm volatile("cp.async.cg.shared.global [%0], [%1], 16;"
                 :: "r"(dst), "l"(src) : "memory");
}
#define CP_COMMIT() asm volatile("cp.async.commit_group;" ::: "memory")
#define CP_WAIT(n)  asm volatile("cp.async.wait_group %0;" :: "n"(n) : "memory")

__device__ __forceinline__ void ldm4(uint32_t* r, uint32_t addr) {
    asm volatile("ldmatrix.sync.aligned.m8n8.x4.shared.b16 {%0,%1,%2,%3}, [%4];"
                 : "=r"(r[0]), "=r"(r[1]), "=r"(r[2]), "=r"(r[3]) : "r"(addr));
}
__device__ __forceinline__ void mma16816(float* c, const uint32_t* a,
                                         uint32_t b0, uint32_t b1) {
    asm volatile(
        "mma.sync.aligned.m16n8k16.row.col.f32.bf16.bf16.f32 "
        "{%0,%1,%2,%3}, {%4,%5,%6,%7}, {%8,%9}, {%0,%1,%2,%3};"
        : "+f"(c[0]), "+f"(c[1]), "+f"(c[2]), "+f"(c[3])
        : "r"(a[0]), "r"(a[1]), "r"(a[2]), "r"(a[3]), "r"(b0), "r"(b1));
}

// smem tile: 128 rows x 32 bf16 (64B/row). 16B-chunk swizzle:
// chunk' = chunk ^ ((row>>1)&3)  -> conflict-free ldmatrix + cp.async
#define SWZB(r, c) (((r) << 6) + (((((c) ^ ((r) >> 1))) & 3) << 4))

// ---------------- quantization ----------------------------------------------
__global__ void k_zero_amax() {
    if (threadIdx.x < 8) g_amax[threadIdx.x] = 0u;
}
__global__ void k_absmax(const float* __restrict__ w, int n, int slot) {
    float m = 0.f;
    for (int i = blockIdx.x * blockDim.x + threadIdx.x; i < n;
         i += gridDim.x * blockDim.x)
        m = fmaxf(m, fabsf(w[i]));
#pragma unroll
    for (int o = 16; o; o >>= 1)
        m = fmaxf(m, __shfl_xor_sync(0xffffffffu, m, o));
    __shared__ float sm[8];
    int wid = threadIdx.x >> 5;
    if ((threadIdx.x & 31) == 0) sm[wid] = m;
    __syncthreads();
    if (threadIdx.x == 0) {
        int nw = blockDim.x >> 5;
        for (int i = 1; i < nw; i++) m = fmaxf(m, sm[i]);
        atomicMax(&g_amax[slot], __float_as_uint(m));
    }
}
__global__ void k_quant(const float* __restrict__ w, float* __restrict__ o,
                        int n, int slot) {
    float amax = __uint_as_float(g_amax[slot]);
    float scale = amax / 31.0f + 1e-8f;
    for (int i = blockIdx.x * blockDim.x + threadIdx.x; i < n;
         i += gridDim.x * blockDim.x) {
        float q = rintf(w[i] / scale);
        q = fminf(fmaxf(q, -31.f), 31.f);
        o[i] = q * scale;
    }
}

// ---------------- fold stalk map into projection -----------------------------
__global__ void k_fold(const float* __restrict__ stalk,
                       const float* __restrict__ w, float* __restrict__ o) {
    int idx = blockIdx.x * 256 + threadIdx.x;
    int r = idx >> 10;
    int kk = idx & 1023;
    int hbase = r & ~63;
    int sp = r & 63;
    float acc = 0.f;
#pragma unroll 8
    for (int s = 0; s < 64; s++)
        acc += stalk[sp * 64 + s] * w[(hbase + s) * 1024 + kk];
    o[idx] = acc;
}

// ---------------- split fp32 -> bf16 hi/lo triple ---------------------------
// pattern 0 (A side): [hi | hi | lo]     pattern 1 (B side): [hi | lo | hi]
__global__ void k_split(const float* __restrict__ in,
                        __nv_bfloat16* __restrict__ out, int K, int pattern) {
    int r = blockIdx.x;
    const float* ir = in + (size_t)r * K;
    __nv_bfloat16* o = out + (size_t)r * 3 * K;
    for (int c = threadIdx.x; c < K; c += blockDim.x) {
        float x = ir[c];
        __nv_bfloat16 hi = __float2bfloat16(x);
        __nv_bfloat16 lo = __float2bfloat16(x - __bfloat162float(hi));
        o[c] = hi;
        if (pattern == 0) { o[K + c] = hi; o[2 * K + c] = lo; }
        else              { o[K + c] = lo; o[2 * K + c] = hi; }
    }
}

// ---------------- layernorm (+silu) fused with A-side split -----------------
__global__ void k_ln(const float* __restrict__ x, const float* __restrict__ g,
                     const float* __restrict__ bb, __nv_bfloat16* __restrict__ out,
                     int n, int do_silu) {
    extern __shared__ float row[];
    int r = blockIdx.x;
    int tid = threadIdx.x;
    const float* xr = x + (size_t)r * n;
    float s = 0.f, s2 = 0.f;
    for (int i = tid; i < n; i += blockDim.x) {
        float v = xr[i];
        row[i] = v;
        s += v;
        s2 += v * v;
    }
#pragma unroll
    for (int o = 16; o; o >>= 1) {
        s += __shfl_xor_sync(0xffffffffu, s, o);
        s2 += __shfl_xor_sync(0xffffffffu, s2, o);
    }
    __shared__ float rs[8], rs2[8];
    __shared__ float mu_s, inv_s;
    int wid = tid >> 5;
    if ((tid & 31) == 0) { rs[wid] = s; rs2[wid] = s2; }
    __syncthreads();
    if (tid == 0) {
        float S = 0.f, S2 = 0.f;
        int nw = blockDim.x >> 5;
        for (int i = 0; i < nw; i++) { S += rs[i]; S2 += rs2[i]; }
        float mu = S / n;
        float var = S2 / n - mu * mu;
        mu_s = mu;
        inv_s = rsqrtf(var + 1e-5f);
    }
    __syncthreads();
    float mu = mu_s, inv = inv_s;
    __nv_bfloat16* orow = out + (size_t)r * 3 * n;
    for (int i = tid; i < n; i += blockDim.x) {
        float y = (row[i] - mu) * inv * g[i] + bb[i];
        if (do_silu) y = y / (1.0f + __expf(-y));
        __nv_bfloat16 hi = __float2bfloat16(y);
        __nv_bfloat16 lo = __float2bfloat16(y - __bfloat162float(hi));
        orow[i] = hi;
        orow[n + i] = hi;
        orow[2 * n + i] = lo;
    }
}

// ---------------- HMMA GEMM: C[M,N] = A'[M,KK] * B'[N,KK]^T -----------------
// 128x128x32 CTA tile, 8 warps (2x4) of 64x32, mma.sync m16n8k16 bf16,
// 3-stage cp.async pipeline, swizzled smem, fused epilogues.
// mode 0: plain   mode 1: C = R + A*B^T   mode 2: SO(2) rotation epilogue
#define STG 3
#define STG_BYTES 16384   // A 8KB + B 8KB

__global__ __launch_bounds__(256, 2)
void k_mma_gemm(const __nv_bfloat16* __restrict__ A,
                const __nv_bfloat16* __restrict__ Bm,
                float* __restrict__ C, const float* __restrict__ R,
                const float* __restrict__ theta, int KK, int N, int mode) {
    extern __shared__ __align__(128) char smraw[];
    uint32_t smb = smem_u32(smraw);
    int tid = threadIdx.x;
    int wid = tid >> 5, lane = tid & 31;
    int wm = wid >> 2, wn = wid & 3;
    int m0 = wm * 64, n0 = wn * 32;
    int bm = blockIdx.y * 128;
    int bn = blockIdx.x * 128;

    float acc[16][4];
#pragma unroll
    for (int i = 0; i < 16; i++)
#pragma unroll
        for (int j = 0; j < 4; j++) acc[i][j] = 0.f;

    const int NC = KK >> 5;

    // load thread mapping: i in [0,512): A rows; [512,1024): B rows
    int r0a = tid >> 2;          // 0..63
    int c0a = tid & 3;
    // prologue: stages 0..STG-2
#pragma unroll
    for (int s = 0; s < STG - 1; s++) {
        uint32_t ab = smb + s * STG_BYTES;
        int kof = s << 5;
#pragma unroll
        for (int half = 0; half < 2; half++) {
            int r = r0a + half * 64;
            cpa16(ab + SWZB(r, c0a), A + (size_t)(bm + r) * KK + kof + c0a * 8);
            cpa16(ab + 8192 + SWZB(r, c0a),
                  Bm + (size_t)(bn + r) * KK + kof + c0a * 8);
        }
        CP_COMMIT();
    }

    for (int kc = 0; kc < NC; kc++) {
        CP_WAIT(STG - 2);
        __syncthreads();
        // prefetch stage kc+STG-1 into buffer just freed
        int nk = kc + STG - 1;
        if (nk < NC) {
            uint32_t ab = smb + (nk % STG) * STG_BYTES;
            int kof = nk << 5;
#pragma unroll
            for (int half = 0; half < 2; half++) {
                int r = r0a + half * 64;
                cpa16(ab + SWZB(r, c0a),
                      A + (size_t)(bm + r) * KK + kof + c0a * 8);
                cpa16(ab + 8192 + SWZB(r, c0a),
                      Bm + (size_t)(bn + r) * KK + kof + c0a * 8);
            }
        }
        CP_COMMIT();

        uint32_t ab = smb + (kc % STG) * STG_BYTES;
        uint32_t bb = ab + 8192;
#pragma unroll
        for (int ks = 0; ks < 2; ks++) {
            uint32_t af[4][4];
            int arow = m0 + (lane & 15);
            int ac = ks * 2 + (lane >> 4);
#pragma unroll
            for (int mt = 0; mt < 4; mt++)
                ldm4(af[mt], ab + SWZB(arow + mt * 16, ac));
            uint32_t bf[2][4];
            int brow = n0 + ((lane >> 4) << 3) + (lane & 7);
            int bc = ks * 2 + ((lane >> 3) & 1);
#pragma unroll
            for (int nt2 = 0; nt2 < 2; nt2++)
                ldm4(bf[nt2], bb + SWZB(brow + nt2 * 16, bc));
#pragma unroll
            for (int mt = 0; mt < 4; mt++)
#pragma unroll
                for (int nt = 0; nt < 4; nt++)
                    mma16816(acc[mt * 4 + nt], af[mt],
                             bf[nt >> 1][(nt & 1) * 2],
                             bf[nt >> 1][(nt & 1) * 2 + 1]);
        }
        __syncthreads();
    }

    // ---- epilogue ----
    int lg = lane >> 2, lt = lane & 3;
#pragma unroll
    for (int mt = 0; mt < 4; mt++) {
#pragma unroll
        for (int nt = 0; nt < 4; nt++) {
            float* cf = acc[mt * 4 + nt];
            int row0 = bm + m0 + mt * 16 + lg;
            int col = bn + n0 + nt * 8 + lt * 2;
            float v0 = cf[0], v1 = cf[1], v2 = cf[2], v3 = cf[3];
            if (mode == 2) {
                float cs, sn;
                __sincosf(theta[col >> 1], &sn, &cs);
                float a0 = v0, b0 = v1, a1 = v2, b1 = v3;
                v0 = cs * a0 - sn * b0;
                v1 = sn * a0 + cs * b0;
                v2 = cs * a1 - sn * b1;
                v3 = sn * a1 + cs * b1;
            }
            if (mode == 1) {
                float2 r0 = *(const float2*)(R + (size_t)row0 * N + col);
                float2 r1 = *(const float2*)(R + (size_t)(row0 + 8) * N + col);
                v0 += r0.x; v1 += r0.y; v2 += r1.x; v3 += r1.y;
            }
            *(float2*)(C + (size_t)row0 * N + col) = make_float2(v0, v1);
            *(float2*)(C + (size_t)(row0 + 8) * N + col) = make_float2(v2, v3);
        }
    }
}

// ---------------- attention (flash-style, p-adic bias on the fly) -----------
#define ATTN_SMEM (4 * 64 * 68 * 4)
#define LDQKV 3072

__global__ __launch_bounds__(256)
void k_attn(const float* __restrict__ QKV, float* __restrict__ O,
            const float* __restrict__ p_scale_ptr) {
    extern __shared__ __align__(16) float smp[];
    float* Qt = smp;
    float* Kt = smp + 64 * 68;
    float* Vs = smp + 2 * 64 * 68;
    float* Pt = smp + 3 * 64 * 68;

    int qt = blockIdx.x, h = blockIdx.y, b = blockIdx.z;
    int tid = threadIdx.x;
    int tx = tid & 15, ty = tid >> 4;
    float ps = p_scale_ptr[0];
    const float scale = 0.125f;

    size_t baseQ = ((size_t)(b * T_) + qt * 64) * LDQKV + h * 64;
#pragma unroll
    for (int i = 0; i < 4; i++) {
        int idx = tid + i * 256;
        int r = idx >> 4;
        int c4 = idx & 15;
        float4 v = *(const float4*)(QKV + baseQ + (size_t)r * LDQKV + c4 * 4);
        Qt[(c4 * 4 + 0) * 68 + r] = v.x;
        Qt[(c4 * 4 + 1) * 68 + r] = v.y;
        Qt[(c4 * 4 + 2) * 68 + r] = v.z;
        Qt[(c4 * 4 + 3) * 68 + r] = v.w;
    }

    float m_i[4], l_i[4], acc[4][4];
#pragma unroll
    for (int i = 0; i < 4; i++) {
        m_i[i] = -1e30f;
        l_i[i] = 0.f;
#pragma unroll
        for (int j = 0; j < 4; j++) acc[i][j] = 0.f;
    }

    for (int jt = 0; jt <= qt; jt++) {
        __syncthreads();
        size_t baseK = ((size_t)(b * T_) + jt * 64) * LDQKV + 1024 + h * 64;
        size_t baseV = baseK + 1024;
#pragma unroll
        for (int i = 0; i < 4; i++) {
            int idx = tid + i * 256;
            int r = idx >> 4;
            int c4 = idx & 15;
            float4 v = *(const float4*)(QKV + baseK + (size_t)r * LDQKV + c4 * 4);
            Kt[(c4 * 4 + 0) * 68 + r] = v.x;
            Kt[(c4 * 4 + 1) * 68 + r] = v.y;
            Kt[(c4 * 4 + 2) * 68 + r] = v.z;
            Kt[(c4 * 4 + 3) * 68 + r] = v.w;
            float4 w = *(const float4*)(QKV + baseV + (size_t)r * LDQKV + c4 * 4);
            *(float4*)&Vs[r * 68 + c4 * 4] = w;
        }
        __syncthreads();

        float sc[4][4];
#pragma unroll
        for (int i = 0; i < 4; i++)
#pragma unroll
            for (int j = 0; j < 4; j++) sc[i][j] = 0.f;
#pragma unroll 8
        for (int s = 0; s < 64; s++) {
            float4 a = *(float4*)&Qt[s * 68 + ty * 4];
            float4 bv = *(float4*)&Kt[s * 68 + tx * 4];
            float av[4] = {a.x, a.y, a.z, a.w};
            float bvv[4] = {bv.x, bv.y, bv.z, bv.w};
#pragma unroll
            for (int i = 0; i < 4; i++)
#pragma unroll
                for (int j = 0; j < 4; j++) sc[i][j] += av[i] * bvv[j];
        }

        int q0 = qt * 64 + ty * 4;
        int k0 = jt * 64 + tx * 4;
#pragma unroll
        for (int i = 0; i < 4; i++) {
#pragma unroll
            for (int j = 0; j < 4; j++) {
                int d = (q0 + i) - (k0 + j);
                if (d < 0) {
                    sc[i][j] = -1e30f;
                } else {
                    float bias = (d == 0) ? 1.0f
                        : fminf((float)(__ffs(d) - 1), 16.f) * 0.0625f;
                    sc[i][j] = sc[i][j] * scale + ps * bias;
                }
            }
        }

#pragma unroll
        for (int i = 0; i < 4; i++) {
            float rm = fmaxf(fmaxf(sc[i][0], sc[i][1]), fmaxf(sc[i][2], sc[i][3]));
#pragma unroll
            for (int o = 1; o < 16; o <<= 1)
                rm = fmaxf(rm, __shfl_xor_sync(0xffffffffu, rm, o));
            float mnew = fmaxf(m_i[i], rm);
            float alpha = __expf(m_i[i] - mnew);
            m_i[i] = mnew;
            float rsum = 0.f;
#pragma unroll
            for (int j = 0; j < 4; j++) {
                float p = __expf(sc[i][j] - mnew);
                sc[i][j] = p;
                rsum += p;
            }
#pragma unroll
            for (int o = 1; o < 16; o <<= 1)
                rsum += __shfl_xor_sync(0xffffffffu, rsum, o);
            l_i[i] = l_i[i] * alpha + rsum;
#pragma unroll
            for (int j = 0; j < 4; j++) acc[i][j] *= alpha;
        }

#pragma unroll
        for (int j = 0; j < 4; j++) {
            float4 p4 = make_float4(sc[0][j], sc[1][j], sc[2][j], sc[3][j]);
            *(float4*)&Pt[(tx * 4 + j) * 68 + ty * 4] = p4;
        }
        __syncthreads();

#pragma unroll 8
        for (int u = 0; u < 64; u++) {
            float4 p = *(float4*)&Pt[u * 68 + ty * 4];
            float4 vv = *(float4*)&Vs[u * 68 + tx * 4];
            float pv[4] = {p.x, p.y, p.z, p.w};
            float vvv[4] = {vv.x, vv.y, vv.z, vv.w};
#pragma unroll
            for (int i = 0; i < 4; i++)
#pragma unroll
                for (int j = 0; j < 4; j++) acc[i][j] += pv[i] * vvv[j];
        }
    }

#pragma unroll
    for (int i = 0; i < 4; i++) {
        float inv = 1.0f / l_i[i];
        float4 o = make_float4(acc[i][0] * inv, acc[i][1] * inv,
                               acc[i][2] * inv, acc[i][3] * inv);
        size_t orow = ((size_t)(b * T_) + qt * 64 + ty * 4 + i) * D_ + h * 64 + tx * 4;
        *(float4*)(O + orow) = o;
    }
}

// ---------------- host orchestration ----------------------------------------
extern "C" void kernel_launch(void* const* d_in, const int* in_sizes, int n_in,
                              void* d_out, int out_size) {
    const float* x      = (const float*)d_in[0];
    const float* wq     = (const float*)d_in[1];
    const float* wk     = (const float*)d_in[2];
    const float* wv     = (const float*)d_in[3];
    const float* wo     = (const float*)d_in[4];
    const float* su     = (const float*)d_in[5];
    const float* sv     = (const float*)d_in[6];
    const float* pscale = (const float*)d_in[7];
    const float* n1g    = (const float*)d_in[8];
    const float* n1b    = (const float*)d_in[9];
    const float* n2g    = (const float*)d_in[10];
    const float* n2b    = (const float*)d_in[11];
    const float* w_up   = (const float*)d_in[12];
    const float* w_down = (const float*)d_in[13];
    const float* theta  = (const float*)d_in[14];
    const float* mg     = (const float*)d_in[15];
    const float* mb     = (const float*)d_in[16];
    float* out = (float*)d_out;

    float *wqq, *wkq, *wvq, *woq, *suq, *svq, *wqf, *wkf, *wupq, *wdnq;
    float *qkv, *att, *x1, *hb;
    __nv_bfloat16 *as_, *acts, *wqkvs, *wos, *wups, *wdns;
    cudaGetSymbolAddress((void**)&wqq, g_wqq);
    cudaGetSymbolAddress((void**)&wkq, g_wkq);
    cudaGetSymbolAddress((void**)&wvq, g_wvq);
    cudaGetSymbolAddress((void**)&woq, g_woq);
    cudaGetSymbolAddress((void**)&suq, g_suq);
    cudaGetSymbolAddress((void**)&svq, g_svq);
    cudaGetSymbolAddress((void**)&wqf, g_wqf);
    cudaGetSymbolAddress((void**)&wkf, g_wkf);
    cudaGetSymbolAddress((void**)&wupq, g_wupq);
    cudaGetSymbolAddress((void**)&wdnq, g_wdnq);
    cudaGetSymbolAddress((void**)&qkv, g_qkv);
    cudaGetSymbolAddress((void**)&att, g_att);
    cudaGetSymbolAddress((void**)&x1, g_x1);
    cudaGetSymbolAddress((void**)&hb, g_h);
    cudaGetSymbolAddress((void**)&as_, g_as);
    cudaGetSymbolAddress((void**)&acts, g_acts);
    cudaGetSymbolAddress((void**)&wqkvs, g_wqkvs);
    cudaGetSymbolAddress((void**)&wos, g_wos);
    cudaGetSymbolAddress((void**)&wups, g_wups);
    cudaGetSymbolAddress((void**)&wdns, g_wdns);

    const int GSM = STG * STG_BYTES;     // 49152
    cudaFuncSetAttribute(k_attn, cudaFuncAttributeMaxDynamicSharedMemorySize,
                         ATTN_SMEM);
    cudaFuncSetAttribute(k_mma_gemm,
                         cudaFuncAttributeMaxDynamicSharedMemorySize, GSM);

    // ---- quantize weights ----
    k_zero_amax<<<1, 32>>>();
    auto ab = [](int n) { int b = (n + 255) / 256; return b > 256 ? 256 : b; };
    k_absmax<<<ab(D_*D_), 256>>>(wq, D_*D_, 0);
    k_absmax<<<ab(D_*D_), 256>>>(wk, D_*D_, 1);
    k_absmax<<<ab(D_*D_), 256>>>(wv, D_*D_, 2);
    k_absmax<<<ab(D_*D_), 256>>>(wo, D_*D_, 3);
    k_absmax<<<ab(S_*S_), 256>>>(su, S_*S_, 4);
    k_absmax<<<ab(S_*S_), 256>>>(sv, S_*S_, 5);
    k_absmax<<<ab(HID_*D_), 256>>>(w_up, HID_*D_, 6);
    k_absmax<<<ab(HID_*D_), 256>>>(w_down, HID_*D_, 7);
    auto qb = [](int n) { int b = (n + 255) / 256; return b > 4096 ? 4096 : b; };
    k_quant<<<qb(D_*D_), 256>>>(wq, wqq, D_*D_, 0);
    k_quant<<<qb(D_*D_), 256>>>(wk, wkq, D_*D_, 1);
    k_quant<<<qb(D_*D_), 256>>>(wv, wvq, D_*D_, 2);
    k_quant<<<qb(D_*D_), 256>>>(wo, woq, D_*D_, 3);
    k_quant<<<qb(S_*S_), 256>>>(su, suq, S_*S_, 4);
    k_quant<<<qb(S_*S_), 256>>>(sv, svq, S_*S_, 5);
    k_quant<<<qb(HID_*D_), 256>>>(w_up, wupq, HID_*D_, 6);
    k_quant<<<qb(HID_*D_), 256>>>(w_down, wdnq, HID_*D_, 7);

    // ---- fold stalk maps into Q/K projections ----
    k_fold<<<(D_*D_)/256, 256>>>(suq, wqq, wqf);
    k_fold<<<(D_*D_)/256, 256>>>(svq, wkq, wkf);

    // ---- split weights to bf16 hi/lo (B pattern) ----
    k_split<<<D_, 256>>>(wqf, wqkvs, D_, 1);
    k_split<<<D_, 256>>>(wkf, wqkvs + (size_t)D_ * KK_D, D_, 1);
    k_split<<<D_, 256>>>(wvq, wqkvs + (size_t)2 * D_ * KK_D, D_, 1);
    k_split<<<D_, 256>>>(woq, wos, D_, 1);
    k_split<<<HID_, 256>>>(wupq, wups, D_, 1);
    k_split<<<D_, 256>>>(wdnq, wdns, HID_, 1);

    // ---- ln1 (fused A-split) ----
    k_ln<<<BT_, 256, D_ * 4>>>(x, n1g, n1b, as_, D_, 0);

    // ---- fused QKV projection ----
    k_mma_gemm<<<dim3(3 * D_ / 128, BT_ / 128), 256, GSM>>>(
        as_, wqkvs, qkv, nullptr, nullptr, KK_D, 3 * D_, 0);

    // ---- attention ----
    k_attn<<<dim3(T_ / 64, H_, B_), 256, ATTN_SMEM>>>(qkv, att, pscale);

    // ---- split att, output projection + residual ----
    k_split<<<BT_, 256>>>(att, as_, D_, 0);
    k_mma_gemm<<<dim3(D_ / 128, BT_ / 128), 256, GSM>>>(
        as_, wos, x1, x, nullptr, KK_D, D_, 1);

    // ---- ln2 (fused A-split) ----
    k_ln<<<BT_, 256, D_ * 4>>>(x1, n2g, n2b, as_, D_, 0);

    // ---- MLP up + SO(2) rotation epilogue ----
    k_mma_gemm<<<dim3(HID_ / 128, BT_ / 128), 256, GSM>>>(
        as_, wups, hb, nullptr, theta, KK_D, HID_, 2);

    // ---- mlp layernorm + silu (fused A-split) ----
    k_ln<<<BT_, 256, HID_ * 4>>>(hb, mg, mb, acts, HID_, 1);

    // ---- MLP down + residual -> output ----
    k_mma_gemm<<<dim3(D_ / 128, BT_ / 128), 256, GSM>>>(
        acts, wdns, out, x1, nullptr, KK_H, D_, 1);
}

// round 5
// speedup vs baseline: 2.3527x; 1.1945x over previous
#include <cuda_runtime.h>
#include <cuda_bf16.h>
#include <math.h>
#include <stdint.h>

// Problem constants
#define B_ 4
#define T_ 1024
#define D_ 1024
#define H_ 16
#define S_ 64
#define HID_ 3072
#define BT_ (B_*T_)

// ---------------- scratch (device globals; no allocation allowed) -----------
__device__ unsigned g_amax[8];
__device__ float g_wqq[D_*D_];
__device__ float g_wkq[D_*D_];
__device__ float g_wvq[D_*D_];
__device__ float g_suq[S_*S_];
__device__ float g_svq[S_*S_];
__device__ float g_qkv[BT_*3*D_];
__device__ float g_x1[BT_*D_];
__device__ float g_h[BT_*HID_];
// bf16 operand buffers
__device__ __nv_bfloat16 g_as[BT_*3*D_];                 // A-side splits (3t or 2t)
__device__ __nv_bfloat16 g_acts[(size_t)BT_*2*HID_];     // mlp act 2-term
__device__ __nv_bfloat16 g_wqkvs[3*D_*3*D_];             // QKV weights 3-term
__device__ __nv_bfloat16 g_wos[D_*2*D_];                 // int 2-term
__device__ __nv_bfloat16 g_wups[HID_*2*D_];              // int 2-term
__device__ __nv_bfloat16 g_wdns[(size_t)D_*2*HID_];      // int 2-term

// ---------------- inline PTX helpers ----------------------------------------
__device__ __forceinline__ uint32_t smem_u32(const void* p) {
    uint32_t a;
    asm("{ .reg .u64 t; cvta.to.shared.u64 t, %1; cvt.u32.u64 %0, t; }"
        : "=r"(a) : "l"(p));
    return a;
}
__device__ __forceinline__ void cpa16(uint32_t dst, const void* src) {
    asm volatile("cp.async.cg.shared.global [%0], [%1], 16;"
                 :: "r"(dst), "l"(src) : "memory");
}
#define CP_COMMIT() asm volatile("cp.async.commit_group;" ::: "memory")
#define CP_WAIT(n)  asm volatile("cp.async.wait_group %0;" :: "n"(n) : "memory")

__device__ __forceinline__ void ldm4(uint32_t* r, uint32_t addr) {
    asm volatile("ldmatrix.sync.aligned.m8n8.x4.shared.b16 {%0,%1,%2,%3}, [%4];"
                 : "=r"(r[0]), "=r"(r[1]), "=r"(r[2]), "=r"(r[3]) : "r"(addr));
}
__device__ __forceinline__ void mma16816(float* c, const uint32_t* a,
                                         uint32_t b0, uint32_t b1) {
    asm volatile(
        "mma.sync.aligned.m16n8k16.row.col.f32.bf16.bf16.f32 "
        "{%0,%1,%2,%3}, {%4,%5,%6,%7}, {%8,%9}, {%0,%1,%2,%3};"
        : "+f"(c[0]), "+f"(c[1]), "+f"(c[2]), "+f"(c[3])
        : "r"(a[0]), "r"(a[1]), "r"(a[2]), "r"(a[3]), "r"(b0), "r"(b1));
}

// smem tile: 128 rows x 32 bf16 (64B/row). 16B-chunk swizzle.
#define SWZB(r, c) (((r) << 6) + (((((c) ^ ((r) >> 1))) & 3) << 4))

// ---------------- fused quantization -----------------------------------------
__global__ void k_zero_amax() {
    if (threadIdx.x < 8) g_amax[threadIdx.x] = 0u;
}

__global__ void k_absmax_all(const float* wq, const float* wk, const float* wv,
                             const float* wo, const float* su, const float* sv,
                             const float* wup, const float* wdn) {
    int slot = blockIdx.y;
    const float* w;
    int n;
    switch (slot) {
        case 0: w = wq; n = D_*D_; break;
        case 1: w = wk; n = D_*D_; break;
        case 2: w = wv; n = D_*D_; break;
        case 3: w = wo; n = D_*D_; break;
        case 4: w = su; n = S_*S_; break;
        case 5: w = sv; n = S_*S_; break;
        case 6: w = wup; n = HID_*D_; break;
        default: w = wdn; n = D_*HID_; break;
    }
    float m = 0.f;
    for (int i = blockIdx.x * blockDim.x + threadIdx.x; i < n;
         i += gridDim.x * blockDim.x)
        m = fmaxf(m, fabsf(w[i]));
#pragma unroll
    for (int o = 16; o; o >>= 1)
        m = fmaxf(m, __shfl_xor_sync(0xffffffffu, m, o));
    __shared__ float sm[8];
    int wid = threadIdx.x >> 5;
    if ((threadIdx.x & 31) == 0) sm[wid] = m;
    __syncthreads();
    if (threadIdx.x == 0) {
        for (int i = 1; i < 8; i++) m = fmaxf(m, sm[i]);
        atomicMax(&g_amax[slot], __float_as_uint(m));
    }
}

// fp slots write k*s (fp32); int slots write k duplicated [k|k] (bf16, exact)
__global__ void k_quant_all(const float* wq, const float* wk, const float* wv,
                            const float* wo, const float* su, const float* sv,
                            const float* wup, const float* wdn) {
    int slot = blockIdx.y;
    const float* src;
    float* fdst = nullptr;
    __nv_bfloat16* idst = nullptr;
    int n, K = 0;
    switch (slot) {
        case 0: src = wq; fdst = g_wqq; n = D_*D_; break;
        case 1: src = wk; fdst = g_wkq; n = D_*D_; break;
        case 2: src = wv; fdst = g_wvq; n = D_*D_; break;
        case 3: src = wo; idst = g_wos; n = D_*D_; K = D_; break;
        case 4: src = su; fdst = g_suq; n = S_*S_; break;
        case 5: src = sv; fdst = g_svq; n = S_*S_; break;
        case 6: src = wup; idst = g_wups; n = HID_*D_; K = D_; break;
        default: src = wdn; idst = g_wdns; n = D_*HID_; K = HID_; break;
    }
    float s = __uint_as_float(g_amax[slot]) / 31.0f + 1e-8f;
    for (int i = blockIdx.x * blockDim.x + threadIdx.x; i < n;
         i += gridDim.x * blockDim.x) {
        float q = rintf(src[i] / s);
        q = fminf(fmaxf(q, -31.f), 31.f);
        if (fdst) {
            fdst[i] = q * s;
        } else {
            int r = i / K, c = i - r * K;
            __nv_bfloat16 kq = __float2bfloat16(q);   // exact: |q|<=31
            idst[(size_t)r * 2 * K + c] = kq;
            idst[(size_t)r * 2 * K + K + c] = kq;
        }
    }
}

// ---------------- fold stalks + 3-term split -> wqkvs ------------------------
// rows 0..1023: su_q @ wq_q ; 1024..2047: sv_q @ wk_q ; 2048..3071: wv_q
// B-side pattern per row: [hi | lo | hi]
__global__ void k_foldsplit() {
    int rowid = blockIdx.x;
    int seg = rowid >> 10;
    int r = rowid & 1023;
    int tid = threadIdx.x;
    __nv_bfloat16* orow = g_wqkvs + (size_t)rowid * 3072;
    if (seg == 2) {
        for (int c = tid; c < 1024; c += 256) {
            float v = g_wvq[r * 1024 + c];
            __nv_bfloat16 hi = __float2bfloat16(v);
            __nv_bfloat16 lo = __float2bfloat16(v - __bfloat162float(hi));
            orow[c] = hi;
            orow[1024 + c] = lo;
            orow[2048 + c] = hi;
        }
        return;
    }
    const float* stalk = seg ? g_svq : g_suq;
    const float* w = seg ? g_wkq : g_wqq;
    int hbase = r & ~63, sp = r & 63;
    __shared__ float srow[64];
    if (tid < 64) srow[tid] = stalk[sp * 64 + tid];
    __syncthreads();
    for (int c = tid; c < 1024; c += 256) {
        float acc = 0.f;
#pragma unroll 8
        for (int s = 0; s < 64; s++)
            acc += srow[s] * w[(hbase + s) * 1024 + c];
        __nv_bfloat16 hi = __float2bfloat16(acc);
        __nv_bfloat16 lo = __float2bfloat16(acc - __bfloat162float(hi));
        orow[c] = hi;
        orow[1024 + c] = lo;
        orow[2048 + c] = hi;
    }
}

// ---------------- layernorm (+silu) fused with A-side split -----------------
// nterm=3: [hi|hi|lo] stride 3n (QKV A pattern); nterm=2: [hi|lo] stride 2n
__global__ void k_ln(const float* __restrict__ x, const float* __restrict__ g,
                     const float* __restrict__ bb, __nv_bfloat16* __restrict__ out,
                     int n, int do_silu, int nterm) {
    extern __shared__ float row[];
    int r = blockIdx.x;
    int tid = threadIdx.x;
    const float* xr = x + (size_t)r * n;
    float s = 0.f, s2 = 0.f;
    for (int i = tid; i < n; i += blockDim.x) {
        float v = xr[i];
        row[i] = v;
        s += v;
        s2 += v * v;
    }
#pragma unroll
    for (int o = 16; o; o >>= 1) {
        s += __shfl_xor_sync(0xffffffffu, s, o);
        s2 += __shfl_xor_sync(0xffffffffu, s2, o);
    }
    __shared__ float rs[8], rs2[8];
    __shared__ float mu_s, inv_s;
    int wid = tid >> 5;
    if ((tid & 31) == 0) { rs[wid] = s; rs2[wid] = s2; }
    __syncthreads();
    if (tid == 0) {
        float S = 0.f, S2 = 0.f;
        int nw = blockDim.x >> 5;
        for (int i = 0; i < nw; i++) { S += rs[i]; S2 += rs2[i]; }
        float mu = S / n;
        float var = S2 / n - mu * mu;
        mu_s = mu;
        inv_s = rsqrtf(var + 1e-5f);
    }
    __syncthreads();
    float mu = mu_s, inv = inv_s;
    __nv_bfloat16* orow = out + (size_t)r * nterm * n;
    for (int i = tid; i < n; i += blockDim.x) {
        float y = (row[i] - mu) * inv * g[i] + bb[i];
        if (do_silu) y = y / (1.0f + __expf(-y));
        __nv_bfloat16 hi = __float2bfloat16(y);
        __nv_bfloat16 lo = __float2bfloat16(y - __bfloat162float(hi));
        if (nterm == 3) {
            orow[i] = hi;
            orow[n + i] = hi;
            orow[2 * n + i] = lo;
        } else {
            orow[i] = hi;
            orow[n + i] = lo;
        }
    }
}

// ---------------- HMMA GEMM: C[M,N] = s * A'[M,KK] * B'[N,KK]^T -------------
// 128x128x32 CTA tile, 8 warps, mma.sync m16n8k16 bf16, 4-stage cp.async,
// one barrier per k-iter. mode 0 plain / 1 +residual / 2 SO(2) rotation.
// slot>=0: multiply accumulator by quant scale from g_amax[slot].
#define STG 4
#define STG_BYTES 16384

__global__ __launch_bounds__(256, 2)
void k_mma_gemm(const __nv_bfloat16* __restrict__ A,
                const __nv_bfloat16* __restrict__ Bm,
                float* __restrict__ C, const float* __restrict__ R,
                const float* __restrict__ theta, int KK, int N, int mode,
                int slot) {
    extern __shared__ __align__(128) char smraw[];
    uint32_t smb = smem_u32(smraw);
    int tid = threadIdx.x;
    int wid = tid >> 5, lane = tid & 31;
    int wm = wid >> 2, wn = wid & 3;
    int m0 = wm * 64, n0 = wn * 32;
    int bm = blockIdx.y * 128;
    int bn = blockIdx.x * 128;

    float acc[16][4];
#pragma unroll
    for (int i = 0; i < 16; i++)
#pragma unroll
        for (int j = 0; j < 4; j++) acc[i][j] = 0.f;

    const int NC = KK >> 5;
    int r0a = tid >> 2;
    int c0a = tid & 3;
#pragma unroll
    for (int s = 0; s < STG - 1; s++) {
        uint32_t ab = smb + s * STG_BYTES;
        int kof = s << 5;
#pragma unroll
        for (int half = 0; half < 2; half++) {
            int r = r0a + half * 64;
            cpa16(ab + SWZB(r, c0a), A + (size_t)(bm + r) * KK + kof + c0a * 8);
            cpa16(ab + 8192 + SWZB(r, c0a),
                  Bm + (size_t)(bn + r) * KK + kof + c0a * 8);
        }
        CP_COMMIT();
    }

    for (int kc = 0; kc < NC; kc++) {
        CP_WAIT(STG - 2);
        __syncthreads();
        int nk = kc + STG - 1;
        if (nk < NC) {
            uint32_t ab = smb + (nk % STG) * STG_BYTES;
            int kof = nk << 5;
#pragma unroll
            for (int half = 0; half < 2; half++) {
                int r = r0a + half * 64;
                cpa16(ab + SWZB(r, c0a),
                      A + (size_t)(bm + r) * KK + kof + c0a * 8);
                cpa16(ab + 8192 + SWZB(r, c0a),
                      Bm + (size_t)(bn + r) * KK + kof + c0a * 8);
            }
        }
        CP_COMMIT();

        uint32_t ab = smb + (kc % STG) * STG_BYTES;
        uint32_t bb = ab + 8192;
#pragma unroll
        for (int ks = 0; ks < 2; ks++) {
            uint32_t af[4][4];
            int arow = m0 + (lane & 15);
            int ac = ks * 2 + (lane >> 4);
#pragma unroll
            for (int mt = 0; mt < 4; mt++)
                ldm4(af[mt], ab + SWZB(arow + mt * 16, ac));
            uint32_t bf[2][4];
            int brow = n0 + ((lane >> 4) << 3) + (lane & 7);
            int bc = ks * 2 + ((lane >> 3) & 1);
#pragma unroll
            for (int nt2 = 0; nt2 < 2; nt2++)
                ldm4(bf[nt2], bb + SWZB(brow + nt2 * 16, bc));
#pragma unroll
            for (int mt = 0; mt < 4; mt++)
#pragma unroll
                for (int nt = 0; nt < 4; nt++)
                    mma16816(acc[mt * 4 + nt], af[mt],
                             bf[nt >> 1][(nt & 1) * 2],
                             bf[nt >> 1][(nt & 1) * 2 + 1]);
        }
    }

    // ---- epilogue ----
    float scl = 1.0f;
    if (slot >= 0)
        scl = __uint_as_float(g_amax[slot]) / 31.0f + 1e-8f;
    int lg = lane >> 2, lt = lane & 3;
#pragma unroll
    for (int mt = 0; mt < 4; mt++) {
#pragma unroll
        for (int nt = 0; nt < 4; nt++) {
            float* cf = acc[mt * 4 + nt];
            int row0 = bm + m0 + mt * 16 + lg;
            int col = bn + n0 + nt * 8 + lt * 2;
            float v0 = cf[0] * scl, v1 = cf[1] * scl;
            float v2 = cf[2] * scl, v3 = cf[3] * scl;
            if (mode == 2) {
                float cs, sn;
                __sincosf(theta[col >> 1], &sn, &cs);
                float a0 = v0, b0 = v1, a1 = v2, b1 = v3;
                v0 = cs * a0 - sn * b0;
                v1 = sn * a0 + cs * b0;
                v2 = cs * a1 - sn * b1;
                v3 = sn * a1 + cs * b1;
            }
            if (mode == 1) {
                float2 r0 = *(const float2*)(R + (size_t)row0 * N + col);
                float2 r1 = *(const float2*)(R + (size_t)(row0 + 8) * N + col);
                v0 += r0.x; v1 += r0.y; v2 += r1.x; v3 += r1.y;
            }
            *(float2*)(C + (size_t)row0 * N + col) = make_float2(v0, v1);
            *(float2*)(C + (size_t)(row0 + 8) * N + col) = make_float2(v2, v3);
        }
    }
}

// ---------------- attention (flash-style, p-adic bias, split-2 epilogue) ----
#define ATTN_SMEM (4 * 64 * 68 * 4)
#define LDQKV 3072

__global__ __launch_bounds__(256)
void k_attn(const float* __restrict__ QKV, __nv_bfloat16* __restrict__ Osplit,
            const float* __restrict__ p_scale_ptr) {
    extern __shared__ __align__(16) float smp[];
    float* Qt = smp;
    float* Kt = smp + 64 * 68;
    float* Vs = smp + 2 * 64 * 68;
    float* Pt = smp + 3 * 64 * 68;

    int qt = blockIdx.x, h = blockIdx.y, b = blockIdx.z;
    int tid = threadIdx.x;
    int tx = tid & 15, ty = tid >> 4;
    float ps = p_scale_ptr[0];
    const float scale = 0.125f;

    size_t baseQ = ((size_t)(b * T_) + qt * 64) * LDQKV + h * 64;
#pragma unroll
    for (int i = 0; i < 4; i++) {
        int idx = tid + i * 256;
        int r = idx >> 4;
        int c4 = idx & 15;
        float4 v = *(const float4*)(QKV + baseQ + (size_t)r * LDQKV + c4 * 4);
        Qt[(c4 * 4 + 0) * 68 + r] = v.x;
        Qt[(c4 * 4 + 1) * 68 + r] = v.y;
        Qt[(c4 * 4 + 2) * 68 + r] = v.z;
        Qt[(c4 * 4 + 3) * 68 + r] = v.w;
    }

    float m_i[4], l_i[4], acc[4][4];
#pragma unroll
    for (int i = 0; i < 4; i++) {
        m_i[i] = -1e30f;
        l_i[i] = 0.f;
#pragma unroll
        for (int j = 0; j < 4; j++) acc[i][j] = 0.f;
    }

    for (int jt = 0; jt <= qt; jt++) {
        __syncthreads();
        size_t baseK = ((size_t)(b * T_) + jt * 64) * LDQKV + 1024 + h * 64;
        size_t baseV = baseK + 1024;
#pragma unroll
        for (int i = 0; i < 4; i++) {
            int idx = tid + i * 256;
            int r = idx >> 4;
            int c4 = idx & 15;
            float4 v = *(const float4*)(QKV + baseK + (size_t)r * LDQKV + c4 * 4);
            Kt[(c4 * 4 + 0) * 68 + r] = v.x;
            Kt[(c4 * 4 + 1) * 68 + r] = v.y;
            Kt[(c4 * 4 + 2) * 68 + r] = v.z;
            Kt[(c4 * 4 + 3) * 68 + r] = v.w;
            float4 w = *(const float4*)(QKV + baseV + (size_t)r * LDQKV + c4 * 4);
            *(float4*)&Vs[r * 68 + c4 * 4] = w;
        }
        __syncthreads();

        float sc[4][4];
#pragma unroll
        for (int i = 0; i < 4; i++)
#pragma unroll
            for (int j = 0; j < 4; j++) sc[i][j] = 0.f;
#pragma unroll 8
        for (int s = 0; s < 64; s++) {
            float4 a = *(float4*)&Qt[s * 68 + ty * 4];
            float4 bv = *(float4*)&Kt[s * 68 + tx * 4];
            float av[4] = {a.x, a.y, a.z, a.w};
            float bvv[4] = {bv.x, bv.y, bv.z, bv.w};
#pragma unroll
            for (int i = 0; i < 4; i++)
#pragma unroll
                for (int j = 0; j < 4; j++) sc[i][j] += av[i] * bvv[j];
        }

        int q0 = qt * 64 + ty * 4;
        int k0 = jt * 64 + tx * 4;
#pragma unroll
        for (int i = 0; i < 4; i++) {
#pragma unroll
            for (int j = 0; j < 4; j++) {
                int d = (q0 + i) - (k0 + j);
                if (d < 0) {
                    sc[i][j] = -1e30f;
                } else {
                    float bias = (d == 0) ? 1.0f
                        : fminf((float)(__ffs(d) - 1), 16.f) * 0.0625f;
                    sc[i][j] = sc[i][j] * scale + ps * bias;
                }
            }
        }

#pragma unroll
        for (int i = 0; i < 4; i++) {
            float rm = fmaxf(fmaxf(sc[i][0], sc[i][1]), fmaxf(sc[i][2], sc[i][3]));
#pragma unroll
            for (int o = 1; o < 16; o <<= 1)
                rm = fmaxf(rm, __shfl_xor_sync(0xffffffffu, rm, o));
            float mnew = fmaxf(m_i[i], rm);
            float alpha = __expf(m_i[i] - mnew);
            m_i[i] = mnew;
            float rsum = 0.f;
#pragma unroll
            for (int j = 0; j < 4; j++) {
                float p = __expf(sc[i][j] - mnew);
                sc[i][j] = p;
                rsum += p;
            }
#pragma unroll
            for (int o = 1; o < 16; o <<= 1)
                rsum += __shfl_xor_sync(0xffffffffu, rsum, o);
            l_i[i] = l_i[i] * alpha + rsum;
#pragma unroll
            for (int j = 0; j < 4; j++) acc[i][j] *= alpha;
        }

#pragma unroll
        for (int j = 0; j < 4; j++) {
            float4 p4 = make_float4(sc[0][j], sc[1][j], sc[2][j], sc[3][j]);
            *(float4*)&Pt[(tx * 4 + j) * 68 + ty * 4] = p4;
        }
        __syncthreads();

#pragma unroll 8
        for (int u = 0; u < 64; u++) {
            float4 p = *(float4*)&Pt[u * 68 + ty * 4];
            float4 vv = *(float4*)&Vs[u * 68 + tx * 4];
            float pv[4] = {p.x, p.y, p.z, p.w};
            float vvv[4] = {vv.x, vv.y, vv.z, vv.w};
#pragma unroll
            for (int i = 0; i < 4; i++)
#pragma unroll
                for (int j = 0; j < 4; j++) acc[i][j] += pv[i] * vvv[j];
        }
    }

    // epilogue: write 2-term [hi|lo] bf16 split, row stride 2048
#pragma unroll
    for (int i = 0; i < 4; i++) {
        float inv = 1.0f / l_i[i];
        size_t orow = ((size_t)(b * T_) + qt * 64 + ty * 4 + i) * 2048;
        int colb = h * 64 + tx * 4;
        __nv_bfloat162 hi2[2], lo2[2];
#pragma unroll
        for (int q = 0; q < 2; q++) {
            float v0 = acc[i][2 * q] * inv;
            float v1 = acc[i][2 * q + 1] * inv;
            __nv_bfloat16 h0 = __float2bfloat16(v0);
            __nv_bfloat16 h1 = __float2bfloat16(v1);
            hi2[q] = __nv_bfloat162(h0, h1);
            lo2[q] = __nv_bfloat162(
                __float2bfloat16(v0 - __bfloat162float(h0)),
                __float2bfloat16(v1 - __bfloat162float(h1)));
        }
        *(__nv_bfloat162*)(Osplit + orow + colb) = hi2[0];
        *(__nv_bfloat162*)(Osplit + orow + colb + 2) = hi2[1];
        *(__nv_bfloat162*)(Osplit + orow + 1024 + colb) = lo2[0];
        *(__nv_bfloat162*)(Osplit + orow + 1024 + colb + 2) = lo2[1];
    }
}

// ---------------- host orchestration ----------------------------------------
extern "C" void kernel_launch(void* const* d_in, const int* in_sizes, int n_in,
                              void* d_out, int out_size) {
    const float* x      = (const float*)d_in[0];
    const float* wq     = (const float*)d_in[1];
    const float* wk     = (const float*)d_in[2];
    const float* wv     = (const float*)d_in[3];
    const float* wo     = (const float*)d_in[4];
    const float* su     = (const float*)d_in[5];
    const float* sv     = (const float*)d_in[6];
    const float* pscale = (const float*)d_in[7];
    const float* n1g    = (const float*)d_in[8];
    const float* n1b    = (const float*)d_in[9];
    const float* n2g    = (const float*)d_in[10];
    const float* n2b    = (const float*)d_in[11];
    const float* w_up   = (const float*)d_in[12];
    const float* w_down = (const float*)d_in[13];
    const float* theta  = (const float*)d_in[14];
    const float* mg     = (const float*)d_in[15];
    const float* mb     = (const float*)d_in[16];
    float* out = (float*)d_out;

    float *qkv, *x1, *hb;
    __nv_bfloat16 *as_, *acts, *wqkvs, *wos, *wups, *wdns;
    cudaGetSymbolAddress((void**)&qkv, g_qkv);
    cudaGetSymbolAddress((void**)&x1, g_x1);
    cudaGetSymbolAddress((void**)&hb, g_h);
    cudaGetSymbolAddress((void**)&as_, g_as);
    cudaGetSymbolAddress((void**)&acts, g_acts);
    cudaGetSymbolAddress((void**)&wqkvs, g_wqkvs);
    cudaGetSymbolAddress((void**)&wos, g_wos);
    cudaGetSymbolAddress((void**)&wups, g_wups);
    cudaGetSymbolAddress((void**)&wdns, g_wdns);

    const int GSM = STG * STG_BYTES;   // 65536
    cudaFuncSetAttribute(k_attn, cudaFuncAttributeMaxDynamicSharedMemorySize,
                         ATTN_SMEM);
    cudaFuncSetAttribute(k_mma_gemm,
                         cudaFuncAttributeMaxDynamicSharedMemorySize, GSM);

    // 1. zero amax
    k_zero_amax<<<1, 32>>>();
    // 2. all absmax in one launch
    k_absmax_all<<<dim3(256, 8), 256>>>(wq, wk, wv, wo, su, sv, w_up, w_down);
    // 3. all quant (+int-dup splits for wo/wup/wdn) in one launch
    k_quant_all<<<dim3(1024, 8), 256>>>(wq, wk, wv, wo, su, sv, w_up, w_down);
    // 4. fold stalks + 3-term split of QKV weights
    k_foldsplit<<<3072, 256>>>();
    // 5. ln1 -> 3-term A split
    k_ln<<<BT_, 256, D_ * 4>>>(x, n1g, n1b, as_, D_, 0, 3);
    // 6. fused QKV projection (profiled launch)
    k_mma_gemm<<<dim3(24, 32), 256, GSM>>>(as_, wqkvs, qkv, nullptr, nullptr,
                                           3 * D_, 3 * D_, 0, -1);
    // 7. attention (epilogue emits 2-term split)
    k_attn<<<dim3(T_ / 64, H_, B_), 256, ATTN_SMEM>>>(qkv, as_, pscale);
    // 8. output projection (int weights, scaled) + residual
    k_mma_gemm<<<dim3(8, 32), 256, GSM>>>(as_, wos, x1, x, nullptr,
                                          2 * D_, D_, 1, 3);
    // 9. ln2 -> 2-term A split
    k_ln<<<BT_, 256, D_ * 4>>>(x1, n2g, n2b, as_, D_, 0, 2);
    // 10. MLP up (int weights, scaled) + SO(2) rotation
    k_mma_gemm<<<dim3(24, 32), 256, GSM>>>(as_, wups, hb, nullptr, theta,
                                           2 * D_, HID_, 2, 6);
    // 11. mlp layernorm + silu -> 2-term A split
    k_ln<<<BT_, 256, HID_ * 4>>>(hb, mg, mb, acts, HID_, 1, 2);
    // 12. MLP down (int weights, scaled) + residual -> out
    k_mma_gemm<<<dim3(8, 32), 256, GSM>>>(acts, wdns, out, x1, nullptr,
                                          2 * HID_, D_, 1, 7);
}

// round 7
// speedup vs baseline: 2.5470x; 1.0826x over previous
#include <cuda_runtime.h>
#include <cuda_bf16.h>
#include <math.h>
#include <stdint.h>

// Problem constants
#define B_ 4
#define T_ 1024
#define D_ 1024
#define H_ 16
#define S_ 64
#define HID_ 3072
#define BT_ (B_*T_)

// ---------------- scratch (device globals; no allocation allowed) -----------
__device__ unsigned g_amax[8];
__device__ float g_wqq[D_*D_];
__device__ float g_wkq[D_*D_];
__device__ float g_suq[S_*S_];
__device__ float g_svq[S_*S_];
__device__ float g_qkv[BT_*3*D_];
__device__ float g_x1[BT_*D_];
__device__ float g_h[BT_*HID_];
__device__ __nv_bfloat16 g_as[BT_*3*D_];
__device__ __nv_bfloat16 g_acts[(size_t)BT_*2*HID_];
__device__ __nv_bfloat16 g_wqkvs[3*D_*3*D_];
__device__ __nv_bfloat16 g_wos[D_*2*D_];
__device__ __nv_bfloat16 g_wups[HID_*2*D_];
__device__ __nv_bfloat16 g_wdns[(size_t)D_*2*HID_];

// ---------------- inline PTX helpers ----------------------------------------
__device__ __forceinline__ uint32_t smem_u32(const void* p) {
    uint32_t a;
    asm("{ .reg .u64 t; cvta.to.shared.u64 t, %1; cvt.u32.u64 %0, t; }"
        : "=r"(a) : "l"(p));
    return a;
}
__device__ __forceinline__ void cpa16(uint32_t dst, const void* src) {
    asm volatile("cp.async.cg.shared.global [%0], [%1], 16;"
                 :: "r"(dst), "l"(src) : "memory");
}
#define CP_COMMIT() asm volatile("cp.async.commit_group;" ::: "memory")
#define CP_WAIT(n)  asm volatile("cp.async.wait_group %0;" :: "n"(n) : "memory")

__device__ __forceinline__ void ldm4(uint32_t* r, uint32_t addr) {
    asm volatile("ldmatrix.sync.aligned.m8n8.x4.shared.b16 {%0,%1,%2,%3}, [%4];"
                 : "=r"(r[0]), "=r"(r[1]), "=r"(r[2]), "=r"(r[3]) : "r"(addr));
}
__device__ __forceinline__ void ldm4t(uint32_t* r, uint32_t addr) {
    asm volatile("ldmatrix.sync.aligned.m8n8.x4.trans.shared.b16 {%0,%1,%2,%3}, [%4];"
                 : "=r"(r[0]), "=r"(r[1]), "=r"(r[2]), "=r"(r[3]) : "r"(addr));
}
__device__ __forceinline__ void mma16816(float* c, const uint32_t* a,
                                         uint32_t b0, uint32_t b1) {
    asm volatile(
        "mma.sync.aligned.m16n8k16.row.col.f32.bf16.bf16.f32 "
        "{%0,%1,%2,%3}, {%4,%5,%6,%7}, {%8,%9}, {%0,%1,%2,%3};"
        : "+f"(c[0]), "+f"(c[1]), "+f"(c[2]), "+f"(c[3])
        : "r"(a[0]), "r"(a[1]), "r"(a[2]), "r"(a[3]), "r"(b0), "r"(b1));
}

#define SWZB(r, c) (((r) << 6) + (((((c) ^ ((r) >> 1))) & 3) << 4))

__device__ __forceinline__ void packhl(uint32_t& dh, uint32_t& dl,
                                       float x0, float x1) {
    __nv_bfloat16 h0 = __float2bfloat16(x0), h1 = __float2bfloat16(x1);
    dh = ((uint32_t)__bfloat16_as_ushort(h1) << 16) | __bfloat16_as_ushort(h0);
    __nv_bfloat16 g0 = __float2bfloat16(x0 - __bfloat162float(h0));
    __nv_bfloat16 g1 = __float2bfloat16(x1 - __bfloat162float(h1));
    dl = ((uint32_t)__bfloat16_as_ushort(g1) << 16) | __bfloat16_as_ushort(g0);
}
__device__ __forceinline__ void store_split(__nv_bfloat16* hi, __nv_bfloat16* lo,
                                            int off, float4 v) {
    uint32_t p01, p23, q01, q23;
    packhl(p01, q01, v.x, v.y);
    packhl(p23, q23, v.z, v.w);
    *(uint2*)(hi + off) = make_uint2(p01, p23);
    *(uint2*)(lo + off) = make_uint2(q01, q23);
}

// ---------------- fused quantization -----------------------------------------
__global__ void k_zero_amax() {
    if (threadIdx.x < 8) g_amax[threadIdx.x] = 0u;
}

__global__ void k_absmax_all(const float* wq, const float* wk, const float* wv,
                             const float* wo, const float* su, const float* sv,
                             const float* wup, const float* wdn) {
    int slot = blockIdx.y;
    const float* w;
    int n;
    switch (slot) {
        case 0: w = wq; n = D_*D_; break;
        case 1: w = wk; n = D_*D_; break;
        case 2: w = wv; n = D_*D_; break;
        case 3: w = wo; n = D_*D_; break;
        case 4: w = su; n = S_*S_; break;
        case 5: w = sv; n = S_*S_; break;
        case 6: w = wup; n = HID_*D_; break;
        default: w = wdn; n = D_*HID_; break;
    }
    float m = 0.f;
    for (int i = blockIdx.x * blockDim.x + threadIdx.x; i < n;
         i += gridDim.x * blockDim.x)
        m = fmaxf(m, fabsf(w[i]));
#pragma unroll
    for (int o = 16; o; o >>= 1)
        m = fmaxf(m, __shfl_xor_sync(0xffffffffu, m, o));
    __shared__ float sm[8];
    int wid = threadIdx.x >> 5;
    if ((threadIdx.x & 31) == 0) sm[wid] = m;
    __syncthreads();
    if (threadIdx.x == 0) {
        for (int i = 1; i < 8; i++) m = fmaxf(m, sm[i]);
        atomicMax(&g_amax[slot], __float_as_uint(m));
    }
}

// wq/wk/su/sv -> fp32 dequant; wv -> split rows 2048.. of g_wqkvs;
// wo/wup/wdn -> integer-code [k|k] bf16 (exact)
__global__ void k_quant_all(const float* wq, const float* wk, const float* wv,
                            const float* wo, const float* su, const float* sv,
                            const float* wup, const float* wdn) {
    int slot = blockIdx.y;
    const float* src;
    float* fdst = nullptr;
    __nv_bfloat16* idst = nullptr;
    int n, K = 0;
    switch (slot) {
        case 0: src = wq; fdst = g_wqq; n = D_*D_; break;
        case 1: src = wk; fdst = g_wkq; n = D_*D_; break;
        case 2: src = wv; n = D_*D_; break;
        case 3: src = wo; idst = g_wos; n = D_*D_; K = D_; break;
        case 4: src = su; fdst = g_suq; n = S_*S_; break;
        case 5: src = sv; fdst = g_svq; n = S_*S_; break;
        case 6: src = wup; idst = g_wups; n = HID_*D_; K = D_; break;
        default: src = wdn; idst = g_wdns; n = D_*HID_; K = HID_; break;
    }
    float s = __uint_as_float(g_amax[slot]) / 31.0f + 1e-8f;
    for (int i = blockIdx.x * blockDim.x + threadIdx.x; i < n;
         i += gridDim.x * blockDim.x) {
        float q = rintf(src[i] / s);
        q = fminf(fmaxf(q, -31.f), 31.f);
        if (fdst) {
            fdst[i] = q * s;
        } else if (idst) {
            int r = i / K, c = i - r * K;
            __nv_bfloat16 kq = __float2bfloat16(q);
            idst[(size_t)r * 2 * K + c] = kq;
            idst[(size_t)r * 2 * K + K + c] = kq;
        } else {           // wv: dequant + split [hi|lo|hi] into rows 2048+
            float v = q * s;
            int r = i >> 10, c = i & 1023;
            __nv_bfloat16 hi = __float2bfloat16(v);
            __nv_bfloat16 lo = __float2bfloat16(v - __bfloat162float(hi));
            size_t base = (size_t)(2048 + r) * 3072;
            g_wqkvs[base + c] = hi;
            g_wqkvs[base + 1024 + c] = lo;
            g_wqkvs[base + 2048 + c] = hi;
        }
    }
}

// ---------------- fold stalks + 3-term split -> wqkvs rows 0..2047 -----------
// 16 output rows per block; weight slab read once per 16 rows.
__global__ void k_foldsplit() {
    int row0 = blockIdx.x * 16;          // 0..2047
    int seg = row0 >> 10;
    int r0 = row0 & 1023;
    int hbase = r0 & ~63;
    int sp0 = r0 & 63;
    const float* stalk = seg ? g_svq : g_suq;
    const float* w = seg ? g_wkq : g_wqq;
    __shared__ float ssm[16][64];
    int tid = threadIdx.x;
    for (int i = tid; i < 16 * 64; i += 256)
        ssm[i >> 6][i & 63] = stalk[(sp0 + (i >> 6)) * 64 + (i & 63)];
    __syncthreads();
    for (int c = tid; c < 1024; c += 256) {
        float acc[16];
#pragma unroll
        for (int i = 0; i < 16; i++) acc[i] = 0.f;
        for (int s = 0; s < 64; s++) {
            float wv = w[(hbase + s) * 1024 + c];
#pragma unroll
            for (int i = 0; i < 16; i++) acc[i] += ssm[i][s] * wv;
        }
#pragma unroll
        for (int i = 0; i < 16; i++) {
            float v = acc[i];
            __nv_bfloat16 hi = __float2bfloat16(v);
            __nv_bfloat16 lo = __float2bfloat16(v - __bfloat162float(hi));
            __nv_bfloat16* orow = g_wqkvs + (size_t)(row0 + i) * 3072;
            orow[c] = hi;
            orow[1024 + c] = lo;
            orow[2048 + c] = hi;
        }
    }
}

// ---------------- layernorm (+silu) fused with A-side split -----------------
__global__ void k_ln(const float* __restrict__ x, const float* __restrict__ g,
                     const float* __restrict__ bb, __nv_bfloat16* __restrict__ out,
                     int n, int do_silu, int nterm) {
    extern __shared__ float row[];
    int r = blockIdx.x;
    int tid = threadIdx.x;
    const float* xr = x + (size_t)r * n;
    float s = 0.f, s2 = 0.f;
    for (int i = tid; i < n; i += blockDim.x) {
        float v = xr[i];
        row[i] = v;
        s += v;
        s2 += v * v;
    }
#pragma unroll
    for (int o = 16; o; o >>= 1) {
        s += __shfl_xor_sync(0xffffffffu, s, o);
        s2 += __shfl_xor_sync(0xffffffffu, s2, o);
    }
    __shared__ float rs[8], rs2[8];
    __shared__ float mu_s, inv_s;
    int wid = tid >> 5;
    if ((tid & 31) == 0) { rs[wid] = s; rs2[wid] = s2; }
    __syncthreads();
    if (tid == 0) {
        float S = 0.f, S2 = 0.f;
        int nw = blockDim.x >> 5;
        for (int i = 0; i < nw; i++) { S += rs[i]; S2 += rs2[i]; }
        float mu = S / n;
        float var = S2 / n - mu * mu;
        mu_s = mu;
        inv_s = rsqrtf(var + 1e-5f);
    }
    __syncthreads();
    float mu = mu_s, inv = inv_s;
    __nv_bfloat16* orow = out + (size_t)r * nterm * n;
    for (int i = tid; i < n; i += blockDim.x) {
        float y = (row[i] - mu) * inv * g[i] + bb[i];
        if (do_silu) y = y / (1.0f + __expf(-y));
        __nv_bfloat16 hi = __float2bfloat16(y);
        __nv_bfloat16 lo = __float2bfloat16(y - __bfloat162float(hi));
        if (nterm == 3) {
            orow[i] = hi;
            orow[n + i] = hi;
            orow[2 * n + i] = lo;
        } else {
            orow[i] = hi;
            orow[n + i] = lo;
        }
    }
}

// ---------------- HMMA GEMM (unchanged from R5) ------------------------------
#define STG 4
#define STG_BYTES 16384

__global__ __launch_bounds__(256, 2)
void k_mma_gemm(const __nv_bfloat16* __restrict__ A,
                const __nv_bfloat16* __restrict__ Bm,
                float* __restrict__ C, const float* __restrict__ R,
                const float* __restrict__ theta, int KK, int N, int mode,
                int slot) {
    extern __shared__ __align__(128) char smraw[];
    uint32_t smb = smem_u32(smraw);
    int tid = threadIdx.x;
    int wid = tid >> 5, lane = tid & 31;
    int wm = wid >> 2, wn = wid & 3;
    int m0 = wm * 64, n0 = wn * 32;
    int bm = blockIdx.y * 128;
    int bn = blockIdx.x * 128;

    float acc[16][4];
#pragma unroll
    for (int i = 0; i < 16; i++)
#pragma unroll
        for (int j = 0; j < 4; j++) acc[i][j] = 0.f;

    const int NC = KK >> 5;
    int r0a = tid >> 2;
    int c0a = tid & 3;
#pragma unroll
    for (int s = 0; s < STG - 1; s++) {
        uint32_t ab = smb + s * STG_BYTES;
        int kof = s << 5;
#pragma unroll
        for (int half = 0; half < 2; half++) {
            int r = r0a + half * 64;
            cpa16(ab + SWZB(r, c0a), A + (size_t)(bm + r) * KK + kof + c0a * 8);
            cpa16(ab + 8192 + SWZB(r, c0a),
                  Bm + (size_t)(bn + r) * KK + kof + c0a * 8);
        }
        CP_COMMIT();
    }

    for (int kc = 0; kc < NC; kc++) {
        CP_WAIT(STG - 2);
        __syncthreads();
        int nk = kc + STG - 1;
        if (nk < NC) {
            uint32_t ab = smb + (nk % STG) * STG_BYTES;
            int kof = nk << 5;
#pragma unroll
            for (int half = 0; half < 2; half++) {
                int r = r0a + half * 64;
                cpa16(ab + SWZB(r, c0a),
                      A + (size_t)(bm + r) * KK + kof + c0a * 8);
                cpa16(ab + 8192 + SWZB(r, c0a),
                      Bm + (size_t)(bn + r) * KK + kof + c0a * 8);
            }
        }
        CP_COMMIT();

        uint32_t ab = smb + (kc % STG) * STG_BYTES;
        uint32_t bb = ab + 8192;
#pragma unroll
        for (int ks = 0; ks < 2; ks++) {
            uint32_t af[4][4];
            int arow = m0 + (lane & 15);
            int ac = ks * 2 + (lane >> 4);
#pragma unroll
            for (int mt = 0; mt < 4; mt++)
                ldm4(af[mt], ab + SWZB(arow + mt * 16, ac));
            uint32_t bf[2][4];
            int brow = n0 + ((lane >> 4) << 3) + (lane & 7);
            int bc = ks * 2 + ((lane >> 3) & 1);
#pragma unroll
            for (int nt2 = 0; nt2 < 2; nt2++)
                ldm4(bf[nt2], bb + SWZB(brow + nt2 * 16, bc));
#pragma unroll
            for (int mt = 0; mt < 4; mt++)
#pragma unroll
                for (int nt = 0; nt < 4; nt++)
                    mma16816(acc[mt * 4 + nt], af[mt],
                             bf[nt >> 1][(nt & 1) * 2],
                             bf[nt >> 1][(nt & 1) * 2 + 1]);
        }
    }

    float scl = 1.0f;
    if (slot >= 0)
        scl = __uint_as_float(g_amax[slot]) / 31.0f + 1e-8f;
    int lg = lane >> 2, lt = lane & 3;
#pragma unroll
    for (int mt = 0; mt < 4; mt++) {
#pragma unroll
        for (int nt = 0; nt < 4; nt++) {
            float* cf = acc[mt * 4 + nt];
            int row0 = bm + m0 + mt * 16 + lg;
            int col = bn + n0 + nt * 8 + lt * 2;
            float v0 = cf[0] * scl, v1 = cf[1] * scl;
            float v2 = cf[2] * scl, v3 = cf[3] * scl;
            if (mode == 2) {
                float cs, sn;
                __sincosf(theta[col >> 1], &sn, &cs);
                float a0 = v0, b0 = v1, a1 = v2, b1 = v3;
                v0 = cs * a0 - sn * b0;
                v1 = sn * a0 + cs * b0;
                v2 = cs * a1 - sn * b1;
                v3 = sn * a1 + cs * b1;
            }
            if (mode == 1) {
                float2 r0 = *(const float2*)(R + (size_t)row0 * N + col);
                float2 r1 = *(const float2*)(R + (size_t)(row0 + 8) * N + col);
                v0 += r0.x; v1 += r0.y; v2 += r1.x; v3 += r1.y;
            }
            *(float2*)(C + (size_t)row0 * N + col) = make_float2(v0, v1);
            *(float2*)(C + (size_t)(row0 + 8) * N + col) = make_float2(v2, v3);
        }
    }
}

// ---------------- tensor-core flash attention --------------------------------
// CTA: 256 thr / 8 warps; q-tile 128 (m16/warp); key tiles 64.
// 3-term splits on QK^T and PV; p-adic bias LUT in smem; warp-level causal skip.
#define ATS 72                        // padded row: 72 bf16 = 144 B
#define ATTN_SMEM2 (((2*128 + 4*64) * ATS) * 2 + 4096)

__global__ __launch_bounds__(256, 1)
void k_attn_tc(const float* __restrict__ QKV, __nv_bfloat16* __restrict__ Osplit,
               const float* __restrict__ ps_ptr) {
    extern __shared__ __align__(16) char sm[];
    __nv_bfloat16* Qhi = (__nv_bfloat16*)sm;
    __nv_bfloat16* Qlo = Qhi + 128 * ATS;
    __nv_bfloat16* Khi = Qlo + 128 * ATS;
    __nv_bfloat16* Klo = Khi + 64 * ATS;
    __nv_bfloat16* Vhi = Klo + 64 * ATS;
    __nv_bfloat16* Vlo = Vhi + 64 * ATS;
    float* bias = (float*)(Vlo + 64 * ATS);

    int Qt = blockIdx.x, h = blockIdx.y, b = blockIdx.z;
    int tid = threadIdx.x, wid = tid >> 5, lane = tid & 31;
    int lg = lane >> 2, lt = lane & 3;
    float ps = ps_ptr[0];

    for (int i = tid; i < 1024; i += 256)
        bias[i] = (i == 0) ? ps
                 : ps * fminf((float)(__ffs(i) - 1), 16.f) * 0.0625f;

    int q0 = Qt * 128;
    size_t rowbase = (size_t)b * 1024;
    for (int e = tid; e < 128 * 16; e += 256) {
        int r = e >> 4, c4 = e & 15;
        float4 v = *(const float4*)(QKV + (rowbase + q0 + r) * 3072 + h * 64 + c4 * 4);
        store_split(Qhi, Qlo, r * ATS + c4 * 4, v);
    }
    __syncthreads();

    uint32_t qh_b = smem_u32(Qhi), ql_b = smem_u32(Qlo);
    uint32_t kh_b = smem_u32(Khi), kl_b = smem_u32(Klo);
    uint32_t vh_b = smem_u32(Vhi), vl_b = smem_u32(Vlo);

    uint32_t aqh[4][4], aql[4][4];
    {
        int arow = wid * 16 + (lane & 15);
        int aoff = (lane >> 4) * 16;
#pragma unroll
        for (int kc = 0; kc < 4; kc++) {
            ldm4(aqh[kc], qh_b + arow * 144 + kc * 32 + aoff);
            ldm4(aql[kc], ql_b + arow * 144 + kc * 32 + aoff);
        }
    }

    float m_i[2] = {-1e30f, -1e30f}, l_i[2] = {0.f, 0.f};
    float oac[8][4];
#pragma unroll
    for (int i = 0; i < 8; i++)
#pragma unroll
        for (int j = 0; j < 4; j++) oac[i][j] = 0.f;

    int wq0 = q0 + wid * 16;
    int ntiles = (Qt + 1) * 2;

    for (int jt = 0; jt < ntiles; jt++) {
        int k0 = jt * 64;
        __syncthreads();
        for (int e = tid; e < 2048; e += 256) {
            int half = e >> 10;
            int r = (e >> 4) & 63, c4 = e & 15;
            float4 v = *(const float4*)(QKV + (rowbase + k0 + r) * 3072 +
                                        (half ? 2048 : 1024) + h * 64 + c4 * 4);
            if (half) store_split(Vhi, Vlo, r * ATS + c4 * 4, v);
            else      store_split(Khi, Klo, r * ATS + c4 * 4, v);
        }
        __syncthreads();
        if (k0 > wq0 + 15) continue;

        float sc[8][4];
#pragma unroll
        for (int i = 0; i < 8; i++)
#pragma unroll
            for (int j = 0; j < 4; j++) sc[i][j] = 0.f;
        {
            int brow = ((lane >> 4) << 3) + (lane & 7);
            int bco = ((lane >> 3) & 1) * 16;
#pragma unroll
            for (int kc = 0; kc < 4; kc++) {
#pragma unroll
                for (int nf2 = 0; nf2 < 4; nf2++) {
                    uint32_t bh[4], bl[4];
                    uint32_t ad = (uint32_t)(nf2 * 16 + brow) * 144 + kc * 32 + bco;
                    ldm4(bh, kh_b + ad);
                    ldm4(bl, kl_b + ad);
                    mma16816(sc[nf2 * 2], aqh[kc], bh[0], bh[1]);
                    mma16816(sc[nf2 * 2], aqh[kc], bl[0], bl[1]);
                    mma16816(sc[nf2 * 2], aql[kc], bh[0], bh[1]);
                    mma16816(sc[nf2 * 2 + 1], aqh[kc], bh[2], bh[3]);
                    mma16816(sc[nf2 * 2 + 1], aqh[kc], bl[2], bl[3]);
                    mma16816(sc[nf2 * 2 + 1], aql[kc], bh[2], bh[3]);
                }
            }
        }
        // bias + causal mask
        int r0t = wq0 + lg, r1t = r0t + 8;
        bool diag = (k0 + 63 > wq0);
#pragma unroll
        for (int nf = 0; nf < 8; nf++) {
            int c0 = k0 + nf * 8 + 2 * lt;
            int d00 = r0t - c0, d01 = d00 - 1;
            int d10 = r1t - c0, d11 = d10 - 1;
            if (diag) {
                sc[nf][0] = (d00 < 0) ? -1e30f : sc[nf][0] * 0.125f + bias[d00];
                sc[nf][1] = (d01 < 0) ? -1e30f : sc[nf][1] * 0.125f + bias[d01];
                sc[nf][2] = (d10 < 0) ? -1e30f : sc[nf][2] * 0.125f + bias[d10];
                sc[nf][3] = (d11 < 0) ? -1e30f : sc[nf][3] * 0.125f + bias[d11];
            } else {
                sc[nf][0] = sc[nf][0] * 0.125f + bias[d00];
                sc[nf][1] = sc[nf][1] * 0.125f + bias[d01];
                sc[nf][2] = sc[nf][2] * 0.125f + bias[d10];
                sc[nf][3] = sc[nf][3] * 0.125f + bias[d11];
            }
        }
        // online softmax
#pragma unroll
        for (int rh = 0; rh < 2; rh++) {
            float rm = -1e30f;
#pragma unroll
            for (int nf = 0; nf < 8; nf++)
                rm = fmaxf(rm, fmaxf(sc[nf][rh * 2], sc[nf][rh * 2 + 1]));
            rm = fmaxf(rm, __shfl_xor_sync(0xffffffffu, rm, 1));
            rm = fmaxf(rm, __shfl_xor_sync(0xffffffffu, rm, 2));
            float mnew = fmaxf(m_i[rh], rm);
            float alpha = __expf(m_i[rh] - mnew);
            m_i[rh] = mnew;
            float rsum = 0.f;
#pragma unroll
            for (int nf = 0; nf < 8; nf++) {
                float p0 = __expf(sc[nf][rh * 2] - mnew);
                float p1 = __expf(sc[nf][rh * 2 + 1] - mnew);
                sc[nf][rh * 2] = p0;
                sc[nf][rh * 2 + 1] = p1;
                rsum += p0 + p1;
            }
            rsum += __shfl_xor_sync(0xffffffffu, rsum, 1);
            rsum += __shfl_xor_sync(0xffffffffu, rsum, 2);
            l_i[rh] = l_i[rh] * alpha + rsum;
#pragma unroll
            for (int nf = 0; nf < 8; nf++) {
                oac[nf][rh * 2] *= alpha;
                oac[nf][rh * 2 + 1] *= alpha;
            }
        }
        // P·V (3-term, P packed from registers)
        {
            int vrow = (lane & 7) + (((lane >> 3) & 1) << 3);
            int vco = ((lane >> 4) & 1) * 16;
#pragma unroll
            for (int uk = 0; uk < 4; uk++) {
                uint32_t ph[4], pl[4];
                packhl(ph[0], pl[0], sc[2 * uk][0], sc[2 * uk][1]);
                packhl(ph[1], pl[1], sc[2 * uk][2], sc[2 * uk][3]);
                packhl(ph[2], pl[2], sc[2 * uk + 1][0], sc[2 * uk + 1][1]);
                packhl(ph[3], pl[3], sc[2 * uk + 1][2], sc[2 * uk + 1][3]);
#pragma unroll
                for (int sf2 = 0; sf2 < 4; sf2++) {
                    uint32_t vh[4], vl[4];
                    uint32_t ad = (uint32_t)(uk * 16 + vrow) * 144 + sf2 * 32 + vco;
                    ldm4t(vh, vh_b + ad);
                    ldm4t(vl, vl_b + ad);
                    mma16816(oac[sf2 * 2], ph, vh[0], vh[1]);
                    mma16816(oac[sf2 * 2], ph, vl[0], vl[1]);
                    mma16816(oac[sf2 * 2], pl, vh[0], vh[1]);
                    mma16816(oac[sf2 * 2 + 1], ph, vh[2], vh[3]);
                    mma16816(oac[sf2 * 2 + 1], ph, vl[2], vl[3]);
                    mma16816(oac[sf2 * 2 + 1], pl, vh[2], vh[3]);
                }
            }
        }
    }
    // epilogue: divide by l, write 2-term [hi|lo] split
#pragma unroll
    for (int rh = 0; rh < 2; rh++) {
        float inv = 1.f / l_i[rh];
        size_t orow = (rowbase + wq0 + lg + rh * 8) * 2048;
#pragma unroll
        for (int nf = 0; nf < 8; nf++) {
            float v0 = oac[nf][rh * 2] * inv;
            float v1 = oac[nf][rh * 2 + 1] * inv;
            uint32_t hp, lp;
            packhl(hp, lp, v0, v1);
            int col = h * 64 + nf * 8 + 2 * lt;
            *(uint32_t*)(Osplit + orow + col) = hp;
            *(uint32_t*)(Osplit + orow + 1024 + col) = lp;
        }
    }
}

// ---------------- host orchestration ----------------------------------------
extern "C" void kernel_launch(void* const* d_in, const int* in_sizes, int n_in,
                              void* d_out, int out_size) {
    const float* x      = (const float*)d_in[0];
    const float* wq     = (const float*)d_in[1];
    const float* wk     = (const float*)d_in[2];
    const float* wv     = (const float*)d_in[3];
    const float* wo     = (const float*)d_in[4];
    const float* su     = (const float*)d_in[5];
    const float* sv     = (const float*)d_in[6];
    const float* pscale = (const float*)d_in[7];
    const float* n1g    = (const float*)d_in[8];
    const float* n1b    = (const float*)d_in[9];
    const float* n2g    = (const float*)d_in[10];
    const float* n2b    = (const float*)d_in[11];
    const float* w_up   = (const float*)d_in[12];
    const float* w_down = (const float*)d_in[13];
    const float* theta  = (const float*)d_in[14];
    const float* mg     = (const float*)d_in[15];
    const float* mb     = (const float*)d_in[16];
    float* out = (float*)d_out;

    float *qkv, *x1, *hb;
    __nv_bfloat16 *as_, *acts, *wqkvs, *wos, *wups, *wdns;
    cudaGetSymbolAddress((void**)&qkv, g_qkv);
    cudaGetSymbolAddress((void**)&x1, g_x1);
    cudaGetSymbolAddress((void**)&hb, g_h);
    cudaGetSymbolAddress((void**)&as_, g_as);
    cudaGetSymbolAddress((void**)&acts, g_acts);
    cudaGetSymbolAddress((void**)&wqkvs, g_wqkvs);
    cudaGetSymbolAddress((void**)&wos, g_wos);
    cudaGetSymbolAddress((void**)&wups, g_wups);
    cudaGetSymbolAddress((void**)&wdns, g_wdns);

    const int GSM = STG * STG_BYTES;
    cudaFuncSetAttribute(k_attn_tc, cudaFuncAttributeMaxDynamicSharedMemorySize,
                         ATTN_SMEM2);
    cudaFuncSetAttribute(k_mma_gemm,
                         cudaFuncAttributeMaxDynamicSharedMemorySize, GSM);

    k_zero_amax<<<1, 32>>>();
    k_absmax_all<<<dim3(256, 8), 256>>>(wq, wk, wv, wo, su, sv, w_up, w_down);
    k_quant_all<<<dim3(1024, 8), 256>>>(wq, wk, wv, wo, su, sv, w_up, w_down);
    k_foldsplit<<<128, 256>>>();
    k_ln<<<BT_, 256, D_ * 4>>>(x, n1g, n1b, as_, D_, 0, 3);
    k_mma_gemm<<<dim3(24, 32), 256, GSM>>>(as_, wqkvs, qkv, nullptr, nullptr,
                                           3 * D_, 3 * D_, 0, -1);
    k_attn_tc<<<dim3(8, 16, 4), 256, ATTN_SMEM2>>>(qkv, as_, pscale);
    k_mma_gemm<<<dim3(8, 32), 256, GSM>>>(as_, wos, x1, x, nullptr,
                                          2 * D_, D_, 1, 3);
    k_ln<<<BT_, 256, D_ * 4>>>(x1, n2g, n2b, as_, D_, 0, 2);
    k_mma_gemm<<<dim3(24, 32), 256, GSM>>>(as_, wups, hb, nullptr, theta,
                                           2 * D_, HID_, 2, 6);
    k_ln<<<BT_, 256, HID_ * 4>>>(hb, mg, mb, acts, HID_, 1, 2);
    k_mma_gemm<<<dim3(8, 32), 256, GSM>>>(acts, wdns, out, x1, nullptr,
                                          2 * HID_, D_, 1, 7);
}

// round 8
// speedup vs baseline: 3.1368x; 1.2316x over previous
#include <cuda_runtime.h>
#include <cuda_bf16.h>
#include <math.h>
#include <stdint.h>

// Problem constants
#define B_ 4
#define T_ 1024
#define D_ 1024
#define H_ 16
#define S_ 64
#define HID_ 3072
#define BT_ (B_*T_)

// ---------------- scratch (device globals; no allocation allowed) -----------
__device__ unsigned g_amax[8];
__device__ float g_wqq[D_*D_];
__device__ float g_wkq[D_*D_];
__device__ float g_suq[S_*S_];
__device__ float g_svq[S_*S_];
__device__ float g_qkv[BT_*3*D_];    // reused as 6 bf16 planes [4096][1024]
__device__ float g_x1[BT_*D_];
__device__ float g_h[BT_*HID_];
__device__ __nv_bfloat16 g_as[BT_*3*D_];
__device__ __nv_bfloat16 g_acts[(size_t)BT_*2*HID_];
__device__ __nv_bfloat16 g_wqkvs[3*D_*3*D_];
__device__ __nv_bfloat16 g_wos[D_*2*D_];
__device__ __nv_bfloat16 g_wups[HID_*2*D_];
__device__ __nv_bfloat16 g_wdns[(size_t)D_*2*HID_];

// ---------------- inline PTX helpers ----------------------------------------
__device__ __forceinline__ uint32_t smem_u32(const void* p) {
    uint32_t a;
    asm("{ .reg .u64 t; cvta.to.shared.u64 t, %1; cvt.u32.u64 %0, t; }"
        : "=r"(a) : "l"(p));
    return a;
}
__device__ __forceinline__ void cpa16(uint32_t dst, const void* src) {
    asm volatile("cp.async.cg.shared.global [%0], [%1], 16;"
                 :: "r"(dst), "l"(src) : "memory");
}
#define CP_COMMIT() asm volatile("cp.async.commit_group;" ::: "memory")
#define CP_WAIT(n)  asm volatile("cp.async.wait_group %0;" :: "n"(n) : "memory")

__device__ __forceinline__ void ldm4(uint32_t* r, uint32_t addr) {
    asm volatile("ldmatrix.sync.aligned.m8n8.x4.shared.b16 {%0,%1,%2,%3}, [%4];"
                 : "=r"(r[0]), "=r"(r[1]), "=r"(r[2]), "=r"(r[3]) : "r"(addr));
}
__device__ __forceinline__ void ldm4t(uint32_t* r, uint32_t addr) {
    asm volatile("ldmatrix.sync.aligned.m8n8.x4.trans.shared.b16 {%0,%1,%2,%3}, [%4];"
                 : "=r"(r[0]), "=r"(r[1]), "=r"(r[2]), "=r"(r[3]) : "r"(addr));
}
__device__ __forceinline__ void mma16816(float* c, const uint32_t* a,
                                         uint32_t b0, uint32_t b1) {
    asm volatile(
        "mma.sync.aligned.m16n8k16.row.col.f32.bf16.bf16.f32 "
        "{%0,%1,%2,%3}, {%4,%5,%6,%7}, {%8,%9}, {%0,%1,%2,%3};"
        : "+f"(c[0]), "+f"(c[1]), "+f"(c[2]), "+f"(c[3])
        : "r"(a[0]), "r"(a[1]), "r"(a[2]), "r"(a[3]), "r"(b0), "r"(b1));
}

#define SWZB(r, c) (((r) << 6) + (((((c) ^ ((r) >> 1))) & 3) << 4))
// 128B-row swizzle: 8 chunks of 16B, chunk' = chunk ^ (row & 7)
#define SWZ128(r, cw) (((r) << 7) + ((((cw) ^ ((r) & 7))) << 4))

__device__ __forceinline__ void packhl(uint32_t& dh, uint32_t& dl,
                                       float x0, float x1) {
    __nv_bfloat16 h0 = __float2bfloat16(x0), h1 = __float2bfloat16(x1);
    dh = ((uint32_t)__bfloat16_as_ushort(h1) << 16) | __bfloat16_as_ushort(h0);
    __nv_bfloat16 g0 = __float2bfloat16(x0 - __bfloat162float(h0));
    __nv_bfloat16 g1 = __float2bfloat16(x1 - __bfloat162float(h1));
    dl = ((uint32_t)__bfloat16_as_ushort(g1) << 16) | __bfloat16_as_ushort(g0);
}

// ---------------- fused quantization -----------------------------------------
__global__ void k_zero_amax() {
    if (threadIdx.x < 8) g_amax[threadIdx.x] = 0u;
}

__global__ void k_absmax_all(const float* wq, const float* wk, const float* wv,
                             const float* wo, const float* su, const float* sv,
                             const float* wup, const float* wdn) {
    int slot = blockIdx.y;
    const float* w;
    int n;
    switch (slot) {
        case 0: w = wq; n = D_*D_; break;
        case 1: w = wk; n = D_*D_; break;
        case 2: w = wv; n = D_*D_; break;
        case 3: w = wo; n = D_*D_; break;
        case 4: w = su; n = S_*S_; break;
        case 5: w = sv; n = S_*S_; break;
        case 6: w = wup; n = HID_*D_; break;
        default: w = wdn; n = D_*HID_; break;
    }
    float m = 0.f;
    for (int i = blockIdx.x * blockDim.x + threadIdx.x; i < n;
         i += gridDim.x * blockDim.x)
        m = fmaxf(m, fabsf(w[i]));
#pragma unroll
    for (int o = 16; o; o >>= 1)
        m = fmaxf(m, __shfl_xor_sync(0xffffffffu, m, o));
    __shared__ float sm[8];
    int wid = threadIdx.x >> 5;
    if ((threadIdx.x & 31) == 0) sm[wid] = m;
    __syncthreads();
    if (threadIdx.x == 0) {
        for (int i = 1; i < 8; i++) m = fmaxf(m, sm[i]);
        atomicMax(&g_amax[slot], __float_as_uint(m));
    }
}

__global__ void k_quant_all(const float* wq, const float* wk, const float* wv,
                            const float* wo, const float* su, const float* sv,
                            const float* wup, const float* wdn) {
    int slot = blockIdx.y;
    const float* src;
    float* fdst = nullptr;
    __nv_bfloat16* idst = nullptr;
    int n, K = 0;
    switch (slot) {
        case 0: src = wq; fdst = g_wqq; n = D_*D_; break;
        case 1: src = wk; fdst = g_wkq; n = D_*D_; break;
        case 2: src = wv; n = D_*D_; break;
        case 3: src = wo; idst = g_wos; n = D_*D_; K = D_; break;
        case 4: src = su; fdst = g_suq; n = S_*S_; break;
        case 5: src = sv; fdst = g_svq; n = S_*S_; break;
        case 6: src = wup; idst = g_wups; n = HID_*D_; K = D_; break;
        default: src = wdn; idst = g_wdns; n = D_*HID_; K = HID_; break;
    }
    float s = __uint_as_float(g_amax[slot]) / 31.0f + 1e-8f;
    for (int i = blockIdx.x * blockDim.x + threadIdx.x; i < n;
         i += gridDim.x * blockDim.x) {
        float q = rintf(src[i] / s);
        q = fminf(fmaxf(q, -31.f), 31.f);
        if (fdst) {
            fdst[i] = q * s;
        } else if (idst) {
            int r = i / K, c = i - r * K;
            __nv_bfloat16 kq = __float2bfloat16(q);
            idst[(size_t)r * 2 * K + c] = kq;
            idst[(size_t)r * 2 * K + K + c] = kq;
        } else {
            float v = q * s;
            int r = i >> 10, c = i & 1023;
            __nv_bfloat16 hi = __float2bfloat16(v);
            __nv_bfloat16 lo = __float2bfloat16(v - __bfloat162float(hi));
            size_t base = (size_t)(2048 + r) * 3072;
            g_wqkvs[base + c] = hi;
            g_wqkvs[base + 1024 + c] = lo;
            g_wqkvs[base + 2048 + c] = hi;
        }
    }
}

// ---------------- fold stalks + 3-term split -> wqkvs rows 0..2047 -----------
// grid (8 colchunks, 128 rowgroups of 16): 1024 blocks.
__global__ void k_foldsplit() {
    int row0 = blockIdx.y * 16;
    int seg = row0 >> 10;
    int r0 = row0 & 1023;
    int hbase = r0 & ~63, sp0 = r0 & 63;
    const float* stalk = seg ? g_svq : g_suq;
    const float* w = seg ? g_wkq : g_wqq;
    __shared__ float ssm[16][64];
    int tid = threadIdx.x;
    for (int i = tid; i < 1024; i += 256)
        ssm[i >> 6][i & 63] = stalk[(sp0 + (i >> 6)) * 64 + (i & 63)];
    __syncthreads();
    int col = blockIdx.x * 128 + (tid & 127);
    int rh = tid >> 7;                       // 0/1 -> rows rh*8..rh*8+7
    float acc[8];
#pragma unroll
    for (int i = 0; i < 8; i++) acc[i] = 0.f;
#pragma unroll 8
    for (int s = 0; s < 64; s++) {
        float wv = w[(hbase + s) * 1024 + col];
#pragma unroll
        for (int i = 0; i < 8; i++) acc[i] += ssm[rh * 8 + i][s] * wv;
    }
#pragma unroll
    for (int i = 0; i < 8; i++) {
        float v = acc[i];
        __nv_bfloat16 hi = __float2bfloat16(v);
        __nv_bfloat16 lo = __float2bfloat16(v - __bfloat162float(hi));
        __nv_bfloat16* orow = g_wqkvs + (size_t)(row0 + rh * 8 + i) * 3072;
        orow[col] = hi;
        orow[1024 + col] = lo;
        orow[2048 + col] = hi;
    }
}

// ---------------- layernorm (+silu) fused with A-side split -----------------
__global__ void k_ln(const float* __restrict__ x, const float* __restrict__ g,
                     const float* __restrict__ bb, __nv_bfloat16* __restrict__ out,
                     int n, int do_silu, int nterm) {
    extern __shared__ float row[];
    int r = blockIdx.x;
    int tid = threadIdx.x;
    const float* xr = x + (size_t)r * n;
    float s = 0.f, s2 = 0.f;
    for (int i = tid; i < n; i += blockDim.x) {
        float v = xr[i];
        row[i] = v;
        s += v;
        s2 += v * v;
    }
#pragma unroll
    for (int o = 16; o; o >>= 1) {
        s += __shfl_xor_sync(0xffffffffu, s, o);
        s2 += __shfl_xor_sync(0xffffffffu, s2, o);
    }
    __shared__ float rs[8], rs2[8];
    __shared__ float mu_s, inv_s;
    int wid = tid >> 5;
    if ((tid & 31) == 0) { rs[wid] = s; rs2[wid] = s2; }
    __syncthreads();
    if (tid == 0) {
        float S = 0.f, S2 = 0.f;
        int nw = blockDim.x >> 5;
        for (int i = 0; i < nw; i++) { S += rs[i]; S2 += rs2[i]; }
        float mu = S / n;
        float var = S2 / n - mu * mu;
        mu_s = mu;
        inv_s = rsqrtf(var + 1e-5f);
    }
    __syncthreads();
    float mu = mu_s, inv = inv_s;
    __nv_bfloat16* orow = out + (size_t)r * nterm * n;
    for (int i = tid; i < n; i += blockDim.x) {
        float y = (row[i] - mu) * inv * g[i] + bb[i];
        if (do_silu) y = y / (1.0f + __expf(-y));
        __nv_bfloat16 hi = __float2bfloat16(y);
        __nv_bfloat16 lo = __float2bfloat16(y - __bfloat162float(hi));
        if (nterm == 3) {
            orow[i] = hi;
            orow[n + i] = hi;
            orow[2 * n + i] = lo;
        } else {
            orow[i] = hi;
            orow[n + i] = lo;
        }
    }
}

// ---------------- HMMA GEMM ---------------------------------------------------
// mode 0 plain / 1 +residual / 2 SO(2) / 3 bf16 hi-lo 6-plane QKV writer
#define STG 4
#define STG_BYTES 16384

__global__ __launch_bounds__(256, 2)
void k_mma_gemm(const __nv_bfloat16* __restrict__ A,
                const __nv_bfloat16* __restrict__ Bm,
                float* __restrict__ C, const float* __restrict__ R,
                const float* __restrict__ theta, int KK, int N, int mode,
                int slot) {
    extern __shared__ __align__(128) char smraw[];
    uint32_t smb = smem_u32(smraw);
    int tid = threadIdx.x;
    int wid = tid >> 5, lane = tid & 31;
    int wm = wid >> 2, wn = wid & 3;
    int m0 = wm * 64, n0 = wn * 32;
    int bm = blockIdx.y * 128;
    int bn = blockIdx.x * 128;

    float acc[16][4];
#pragma unroll
    for (int i = 0; i < 16; i++)
#pragma unroll
        for (int j = 0; j < 4; j++) acc[i][j] = 0.f;

    const int NC = KK >> 5;
    int r0a = tid >> 2;
    int c0a = tid & 3;
#pragma unroll
    for (int s = 0; s < STG - 1; s++) {
        uint32_t ab = smb + s * STG_BYTES;
        int kof = s << 5;
#pragma unroll
        for (int half = 0; half < 2; half++) {
            int r = r0a + half * 64;
            cpa16(ab + SWZB(r, c0a), A + (size_t)(bm + r) * KK + kof + c0a * 8);
            cpa16(ab + 8192 + SWZB(r, c0a),
                  Bm + (size_t)(bn + r) * KK + kof + c0a * 8);
        }
        CP_COMMIT();
    }

    for (int kc = 0; kc < NC; kc++) {
        CP_WAIT(STG - 2);
        __syncthreads();
        int nk = kc + STG - 1;
        if (nk < NC) {
            uint32_t ab = smb + (nk % STG) * STG_BYTES;
            int kof = nk << 5;
#pragma unroll
            for (int half = 0; half < 2; half++) {
                int r = r0a + half * 64;
                cpa16(ab + SWZB(r, c0a),
                      A + (size_t)(bm + r) * KK + kof + c0a * 8);
                cpa16(ab + 8192 + SWZB(r, c0a),
                      Bm + (size_t)(bn + r) * KK + kof + c0a * 8);
            }
        }
        CP_COMMIT();

        uint32_t ab = smb + (kc % STG) * STG_BYTES;
        uint32_t bb = ab + 8192;
#pragma unroll
        for (int ks = 0; ks < 2; ks++) {
            uint32_t af[4][4];
            int arow = m0 + (lane & 15);
            int ac = ks * 2 + (lane >> 4);
#pragma unroll
            for (int mt = 0; mt < 4; mt++)
                ldm4(af[mt], ab + SWZB(arow + mt * 16, ac));
            uint32_t bf[2][4];
            int brow = n0 + ((lane >> 4) << 3) + (lane & 7);
            int bc = ks * 2 + ((lane >> 3) & 1);
#pragma unroll
            for (int nt2 = 0; nt2 < 2; nt2++)
                ldm4(bf[nt2], bb + SWZB(brow + nt2 * 16, bc));
#pragma unroll
            for (int mt = 0; mt < 4; mt++)
#pragma unroll
                for (int nt = 0; nt < 4; nt++)
                    mma16816(acc[mt * 4 + nt], af[mt],
                             bf[nt >> 1][(nt & 1) * 2],
                             bf[nt >> 1][(nt & 1) * 2 + 1]);
        }
    }

    float scl = 1.0f;
    if (slot >= 0)
        scl = __uint_as_float(g_amax[slot]) / 31.0f + 1e-8f;
    int lg = lane >> 2, lt = lane & 3;
#pragma unroll
    for (int mt = 0; mt < 4; mt++) {
#pragma unroll
        for (int nt = 0; nt < 4; nt++) {
            float* cf = acc[mt * 4 + nt];
            int row0 = bm + m0 + mt * 16 + lg;
            int col = bn + n0 + nt * 8 + lt * 2;
            float v0 = cf[0] * scl, v1 = cf[1] * scl;
            float v2 = cf[2] * scl, v3 = cf[3] * scl;
            if (mode == 3) {
                // write bf16 hi/lo planes: seg 0 Q / 1 K / 2 V
                __nv_bfloat16* P = (__nv_bfloat16*)C;
                int seg = col >> 10, c = col & 1023;
                size_t PL = (size_t)4096 * 1024;
                uint32_t h01, l01, h23, l23;
                packhl(h01, l01, v0, v1);
                packhl(h23, l23, v2, v3);
                size_t o0 = (size_t)row0 * 1024 + c;
                size_t o1 = (size_t)(row0 + 8) * 1024 + c;
                *(uint32_t*)(P + 2 * seg * PL + o0) = h01;
                *(uint32_t*)(P + (2 * seg + 1) * PL + o0) = l01;
                *(uint32_t*)(P + 2 * seg * PL + o1) = h23;
                *(uint32_t*)(P + (2 * seg + 1) * PL + o1) = l23;
                continue;
            }
            if (mode == 2) {
                float cs, sn;
                __sincosf(theta[col >> 1], &sn, &cs);
                float a0 = v0, b0 = v1, a1 = v2, b1 = v3;
                v0 = cs * a0 - sn * b0;
                v1 = sn * a0 + cs * b0;
                v2 = cs * a1 - sn * b1;
                v3 = sn * a1 + cs * b1;
            }
            if (mode == 1) {
                float2 r0 = *(const float2*)(R + (size_t)row0 * N + col);
                float2 r1 = *(const float2*)(R + (size_t)(row0 + 8) * N + col);
                v0 += r0.x; v1 += r0.y; v2 += r1.x; v3 += r1.y;
            }
            *(float2*)(C + (size_t)row0 * N + col) = make_float2(v0, v1);
            *(float2*)(C + (size_t)(row0 + 8) * N + col) = make_float2(v2, v3);
        }
    }
}

// ---------------- tensor-core flash attention (bf16 planes, pipelined) -------
// smem: Qh 0, Ql 16K, KV stage s at 32K+s*32K {Kh,Kl,Vh,Vl 8K each}, bias 96K+2K
#define ATTN_SMEM3 (98304 + 4096)

__global__ __launch_bounds__(256, 1)
void k_attn_tc(const __nv_bfloat16* __restrict__ QS,
               __nv_bfloat16* __restrict__ Osplit,
               const float* __restrict__ ps_ptr) {
    extern __shared__ __align__(16) char sm[];
    uint32_t smb = smem_u32(sm);
    float* bias = (float*)(sm + 98304);
    int Qt = blockIdx.x, h = blockIdx.y, b = blockIdx.z;
    int tid = threadIdx.x, wid = tid >> 5, lane = tid & 31;
    int lg = lane >> 2, lt = lane & 3;
    float ps = ps_ptr[0];
    for (int i = tid; i < 1024; i += 256)
        bias[i] = (i == 0) ? ps
                 : ps * fminf((float)(__ffs(i) - 1), 16.f) * 0.0625f;

    const size_t PL = (size_t)4096 * 1024;
    size_t rowbase = (size_t)b * 1024;
    int colb = h * 64;
    int q0 = Qt * 128;

    // prologue group: Q (2 planes, 128 rows) + KV tile 0 (4 subtiles, 64 rows)
    for (int e = tid; e < 2048; e += 256) {
        int pl = e >> 10;
        int r = (e >> 3) & 127, cw = e & 7;
        cpa16(smb + pl * 16384 + SWZ128(r, cw),
              QS + pl * PL + (rowbase + q0 + r) * 1024 + colb + cw * 8);
    }
    for (int e = tid; e < 2048; e += 256) {
        int sub = e >> 9;
        int r = (e >> 3) & 63, cw = e & 7;
        cpa16(smb + 32768 + sub * 8192 + SWZ128(r, cw),
              QS + (2 + sub) * PL + (rowbase + r) * 1024 + colb + cw * 8);
    }
    CP_COMMIT();

    uint32_t aqh[4][4], aql[4][4];
    float m_i[2] = {-1e30f, -1e30f}, l_i[2] = {0.f, 0.f};
    float oac[8][4];
#pragma unroll
    for (int i = 0; i < 8; i++)
#pragma unroll
        for (int j = 0; j < 4; j++) oac[i][j] = 0.f;

    int wq0 = q0 + wid * 16;
    int ntiles = (Qt + 1) * 2;

    for (int jt = 0; jt < ntiles; jt++) {
        if (jt + 1 < ntiles) {
            int k0n = (jt + 1) * 64;
            uint32_t stb = smb + 32768 + ((jt + 1) & 1) * 32768;
            for (int e = tid; e < 2048; e += 256) {
                int sub = e >> 9;
                int r = (e >> 3) & 63, cw = e & 7;
                cpa16(stb + sub * 8192 + SWZ128(r, cw),
                      QS + (2 + sub) * PL + (rowbase + k0n + r) * 1024 + colb + cw * 8);
            }
            CP_COMMIT();
            CP_WAIT(1);
        } else {
            CP_WAIT(0);
        }
        __syncthreads();
        if (jt == 0) {
            int arow = wid * 16 + (lane & 15);
            int khalf = lane >> 4;
#pragma unroll
            for (int kc = 0; kc < 4; kc++) {
                uint32_t ad = SWZ128(arow, kc * 2 + khalf);
                ldm4(aqh[kc], smb + ad);
                ldm4(aql[kc], smb + 16384 + ad);
            }
        }
        int k0 = jt * 64;
        uint32_t stb = smb + 32768 + (jt & 1) * 32768;
        if (k0 <= wq0 + 15) {
            float sc[8][4];
#pragma unroll
            for (int i = 0; i < 8; i++)
#pragma unroll
                for (int j = 0; j < 4; j++) sc[i][j] = 0.f;
            {
                int brow = ((lane >> 4) << 3) + (lane & 7);
                int bhalf = (lane >> 3) & 1;
#pragma unroll
                for (int kc = 0; kc < 4; kc++) {
#pragma unroll
                    for (int nf2 = 0; nf2 < 4; nf2++) {
                        uint32_t bh[4], bl[4];
                        uint32_t ad = SWZ128(nf2 * 16 + brow, kc * 2 + bhalf);
                        ldm4(bh, stb + ad);
                        ldm4(bl, stb + 8192 + ad);
                        mma16816(sc[nf2 * 2], aqh[kc], bh[0], bh[1]);
                        mma16816(sc[nf2 * 2], aqh[kc], bl[0], bl[1]);
                        mma16816(sc[nf2 * 2], aql[kc], bh[0], bh[1]);
                        mma16816(sc[nf2 * 2 + 1], aqh[kc], bh[2], bh[3]);
                        mma16816(sc[nf2 * 2 + 1], aqh[kc], bl[2], bl[3]);
                        mma16816(sc[nf2 * 2 + 1], aql[kc], bh[2], bh[3]);
                    }
                }
            }
            int r0t = wq0 + lg, r1t = r0t + 8;
            bool diag = (k0 + 63 > wq0);
#pragma unroll
            for (int nf = 0; nf < 8; nf++) {
                int c0 = k0 + nf * 8 + 2 * lt;
                int d00 = r0t - c0, d01 = d00 - 1;
                int d10 = r1t - c0, d11 = d10 - 1;
                if (diag) {
                    sc[nf][0] = (d00 < 0) ? -1e30f : sc[nf][0] * 0.125f + bias[d00];
                    sc[nf][1] = (d01 < 0) ? -1e30f : sc[nf][1] * 0.125f + bias[d01];
                    sc[nf][2] = (d10 < 0) ? -1e30f : sc[nf][2] * 0.125f + bias[d10];
                    sc[nf][3] = (d11 < 0) ? -1e30f : sc[nf][3] * 0.125f + bias[d11];
                } else {
                    sc[nf][0] = sc[nf][0] * 0.125f + bias[d00];
                    sc[nf][1] = sc[nf][1] * 0.125f + bias[d01];
                    sc[nf][2] = sc[nf][2] * 0.125f + bias[d10];
                    sc[nf][3] = sc[nf][3] * 0.125f + bias[d11];
                }
            }
#pragma unroll
            for (int rh = 0; rh < 2; rh++) {
                float rm = -1e30f;
#pragma unroll
                for (int nf = 0; nf < 8; nf++)
                    rm = fmaxf(rm, fmaxf(sc[nf][rh * 2], sc[nf][rh * 2 + 1]));
                rm = fmaxf(rm, __shfl_xor_sync(0xffffffffu, rm, 1));
                rm = fmaxf(rm, __shfl_xor_sync(0xffffffffu, rm, 2));
                float mnew = fmaxf(m_i[rh], rm);
                float alpha = __expf(m_i[rh] - mnew);
                m_i[rh] = mnew;
                float rsum = 0.f;
#pragma unroll
                for (int nf = 0; nf < 8; nf++) {
                    float p0 = __expf(sc[nf][rh * 2] - mnew);
                    float p1 = __expf(sc[nf][rh * 2 + 1] - mnew);
                    sc[nf][rh * 2] = p0;
                    sc[nf][rh * 2 + 1] = p1;
                    rsum += p0 + p1;
                }
                rsum += __shfl_xor_sync(0xffffffffu, rsum, 1);
                rsum += __shfl_xor_sync(0xffffffffu, rsum, 2);
                l_i[rh] = l_i[rh] * alpha + rsum;
#pragma unroll
                for (int nf = 0; nf < 8; nf++) {
                    oac[nf][rh * 2] *= alpha;
                    oac[nf][rh * 2 + 1] *= alpha;
                }
            }
            {
                int vrow = (lane & 7) + (((lane >> 3) & 1) << 3);
                int vhalf = (lane >> 4) & 1;
#pragma unroll
                for (int uk = 0; uk < 4; uk++) {
                    uint32_t ph[4], pl[4];
                    packhl(ph[0], pl[0], sc[2 * uk][0], sc[2 * uk][1]);
                    packhl(ph[1], pl[1], sc[2 * uk][2], sc[2 * uk][3]);
                    packhl(ph[2], pl[2], sc[2 * uk + 1][0], sc[2 * uk + 1][1]);
                    packhl(ph[3], pl[3], sc[2 * uk + 1][2], sc[2 * uk + 1][3]);
#pragma unroll
                    for (int sf2 = 0; sf2 < 4; sf2++) {
                        uint32_t vh[4], vl[4];
                        uint32_t ad = SWZ128(uk * 16 + vrow, sf2 * 2 + vhalf);
                        ldm4t(vh, stb + 16384 + ad);
                        ldm4t(vl, stb + 24576 + ad);
                        mma16816(oac[sf2 * 2], ph, vh[0], vh[1]);
                        mma16816(oac[sf2 * 2], ph, vl[0], vl[1]);
                        mma16816(oac[sf2 * 2], pl, vh[0], vh[1]);
                        mma16816(oac[sf2 * 2 + 1], ph, vh[2], vh[3]);
                        mma16816(oac[sf2 * 2 + 1], ph, vl[2], vl[3]);
                        mma16816(oac[sf2 * 2 + 1], pl, vh[2], vh[3]);
                    }
                }
            }
        }
        __syncthreads();
    }
#pragma unroll
    for (int rh = 0; rh < 2; rh++) {
        float inv = 1.f / l_i[rh];
        size_t orow = (rowbase + wq0 + lg + rh * 8) * 2048;
#pragma unroll
        for (int nf = 0; nf < 8; nf++) {
            float v0 = oac[nf][rh * 2] * inv;
            float v1 = oac[nf][rh * 2 + 1] * inv;
            uint32_t hp, lp;
            packhl(hp, lp, v0, v1);
            int col = h * 64 + nf * 8 + 2 * lt;
            *(uint32_t*)(Osplit + orow + col) = hp;
            *(uint32_t*)(Osplit + orow + 1024 + col) = lp;
        }
    }
}

// ---------------- host orchestration ----------------------------------------
extern "C" void kernel_launch(void* const* d_in, const int* in_sizes, int n_in,
                              void* d_out, int out_size) {
    const float* x      = (const float*)d_in[0];
    const float* wq     = (const float*)d_in[1];
    const float* wk     = (const float*)d_in[2];
    const float* wv     = (const float*)d_in[3];
    const float* wo     = (const float*)d_in[4];
    const float* su     = (const float*)d_in[5];
    const float* sv     = (const float*)d_in[6];
    const float* pscale = (const float*)d_in[7];
    const float* n1g    = (const float*)d_in[8];
    const float* n1b    = (const float*)d_in[9];
    const float* n2g    = (const float*)d_in[10];
    const float* n2b    = (const float*)d_in[11];
    const float* w_up   = (const float*)d_in[12];
    const float* w_down = (const float*)d_in[13];
    const float* theta  = (const float*)d_in[14];
    const float* mg     = (const float*)d_in[15];
    const float* mb     = (const float*)d_in[16];
    float* out = (float*)d_out;

    float *qkv, *x1, *hb;
    __nv_bfloat16 *as_, *acts, *wqkvs, *wos, *wups, *wdns;
    cudaGetSymbolAddress((void**)&qkv, g_qkv);
    cudaGetSymbolAddress((void**)&x1, g_x1);
    cudaGetSymbolAddress((void**)&hb, g_h);
    cudaGetSymbolAddress((void**)&as_, g_as);
    cudaGetSymbolAddress((void**)&acts, g_acts);
    cudaGetSymbolAddress((void**)&wqkvs, g_wqkvs);
    cudaGetSymbolAddress((void**)&wos, g_wos);
    cudaGetSymbolAddress((void**)&wups, g_wups);
    cudaGetSymbolAddress((void**)&wdns, g_wdns);

    const int GSM = STG * STG_BYTES;
    cudaFuncSetAttribute(k_attn_tc, cudaFuncAttributeMaxDynamicSharedMemorySize,
                         ATTN_SMEM3);
    cudaFuncSetAttribute(k_mma_gemm,
                         cudaFuncAttributeMaxDynamicSharedMemorySize, GSM);

    k_zero_amax<<<1, 32>>>();
    k_absmax_all<<<dim3(256, 8), 256>>>(wq, wk, wv, wo, su, sv, w_up, w_down);
    k_quant_all<<<dim3(1024, 8), 256>>>(wq, wk, wv, wo, su, sv, w_up, w_down);
    k_foldsplit<<<dim3(8, 128), 256>>>();
    k_ln<<<BT_, 256, D_ * 4>>>(x, n1g, n1b, as_, D_, 0, 3);
    k_mma_gemm<<<dim3(24, 32), 256, GSM>>>(as_, wqkvs, qkv, nullptr, nullptr,
                                           3 * D_, 3 * D_, 3, -1);
    k_attn_tc<<<dim3(8, 16, 4), 256, ATTN_SMEM3>>>(
        (const __nv_bfloat16*)qkv, as_, pscale);
    k_mma_gemm<<<dim3(8, 32), 256, GSM>>>(as_, wos, x1, x, nullptr,
                                          2 * D_, D_, 1, 3);
    k_ln<<<BT_, 256, D_ * 4>>>(x1, n2g, n2b, as_, D_, 0, 2);
    k_mma_gemm<<<dim3(24, 32), 256, GSM>>>(as_, wups, hb, nullptr, theta,
                                           2 * D_, HID_, 2, 6);
    k_ln<<<BT_, 256, HID_ * 4>>>(hb, mg, mb, acts, HID_, 1, 2);
    k_mma_gemm<<<dim3(8, 32), 256, GSM>>>(acts, wdns, out, x1, nullptr,
                                          2 * HID_, D_, 1, 7);
}

// round 9
// speedup vs baseline: 3.4706x; 1.1064x over previous
#include <cuda_runtime.h>
#include <cuda_bf16.h>
#include <math.h>
#include <stdint.h>

// Problem constants
#define B_ 4
#define T_ 1024
#define D_ 1024
#define H_ 16
#define S_ 64
#define HID_ 3072
#define BT_ (B_*T_)

// ---------------- scratch (device globals; no allocation allowed) -----------
__device__ unsigned g_amax[8];
__device__ float g_suq[S_*S_];
__device__ float g_svq[S_*S_];
__device__ __align__(16) __nv_bfloat16 g_Mt[2*64*64];   // M^T hi | lo
__device__ float g_qkv[BT_*3*D_];    // reused as 6 bf16 planes [4096][1024]
__device__ float g_x1[BT_*D_];
__device__ float g_h[BT_*HID_];
__device__ __nv_bfloat16 g_as[BT_*3*D_];
__device__ __nv_bfloat16 g_acts[(size_t)BT_*2*HID_];
__device__ __nv_bfloat16 g_wqkvs[3*D_*2*D_];            // int codes [k|k], QKV rows
__device__ __nv_bfloat16 g_wos[D_*2*D_];
__device__ __nv_bfloat16 g_wups[HID_*2*D_];
__device__ __nv_bfloat16 g_wdns[(size_t)D_*2*HID_];

// ---------------- inline PTX helpers ----------------------------------------
__device__ __forceinline__ uint32_t smem_u32(const void* p) {
    uint32_t a;
    asm("{ .reg .u64 t; cvta.to.shared.u64 t, %1; cvt.u32.u64 %0, t; }"
        : "=r"(a) : "l"(p));
    return a;
}
__device__ __forceinline__ void cpa16(uint32_t dst, const void* src) {
    asm volatile("cp.async.cg.shared.global [%0], [%1], 16;"
                 :: "r"(dst), "l"(src) : "memory");
}
#define CP_COMMIT() asm volatile("cp.async.commit_group;" ::: "memory")
#define CP_WAIT(n)  asm volatile("cp.async.wait_group %0;" :: "n"(n) : "memory")

__device__ __forceinline__ void ldm4(uint32_t* r, uint32_t addr) {
    asm volatile("ldmatrix.sync.aligned.m8n8.x4.shared.b16 {%0,%1,%2,%3}, [%4];"
                 : "=r"(r[0]), "=r"(r[1]), "=r"(r[2]), "=r"(r[3]) : "r"(addr));
}
__device__ __forceinline__ void ldm4t(uint32_t* r, uint32_t addr) {
    asm volatile("ldmatrix.sync.aligned.m8n8.x4.trans.shared.b16 {%0,%1,%2,%3}, [%4];"
                 : "=r"(r[0]), "=r"(r[1]), "=r"(r[2]), "=r"(r[3]) : "r"(addr));
}
__device__ __forceinline__ void mma16816(float* c, const uint32_t* a,
                                         uint32_t b0, uint32_t b1) {
    asm volatile(
        "mma.sync.aligned.m16n8k16.row.col.f32.bf16.bf16.f32 "
        "{%0,%1,%2,%3}, {%4,%5,%6,%7}, {%8,%9}, {%0,%1,%2,%3};"
        : "+f"(c[0]), "+f"(c[1]), "+f"(c[2]), "+f"(c[3])
        : "r"(a[0]), "r"(a[1]), "r"(a[2]), "r"(a[3]), "r"(b0), "r"(b1));
}

#define SWZB(r, c) (((r) << 6) + (((((c) ^ ((r) >> 1))) & 3) << 4))
#define SWZ128(r, cw) (((r) << 7) + ((((cw) ^ ((r) & 7))) << 4))

__device__ __forceinline__ void packhl(uint32_t& dh, uint32_t& dl,
                                       float x0, float x1) {
    __nv_bfloat16 h0 = __float2bfloat16(x0), h1 = __float2bfloat16(x1);
    dh = ((uint32_t)__bfloat16_as_ushort(h1) << 16) | __bfloat16_as_ushort(h0);
    __nv_bfloat16 g0 = __float2bfloat16(x0 - __bfloat162float(h0));
    __nv_bfloat16 g1 = __float2bfloat16(x1 - __bfloat162float(h1));
    dl = ((uint32_t)__bfloat16_as_ushort(g1) << 16) | __bfloat16_as_ushort(g0);
}

// ---------------- fused quantization -----------------------------------------
__global__ void k_zero_amax() {
    if (threadIdx.x < 8) g_amax[threadIdx.x] = 0u;
}

__global__ void k_absmax_all(const float* wq, const float* wk, const float* wv,
                             const float* wo, const float* su, const float* sv,
                             const float* wup, const float* wdn) {
    int slot = blockIdx.y;
    const float* w;
    int n;
    switch (slot) {
        case 0: w = wq; n = D_*D_; break;
        case 1: w = wk; n = D_*D_; break;
        case 2: w = wv; n = D_*D_; break;
        case 3: w = wo; n = D_*D_; break;
        case 4: w = su; n = S_*S_; break;
        case 5: w = sv; n = S_*S_; break;
        case 6: w = wup; n = HID_*D_; break;
        default: w = wdn; n = D_*HID_; break;
    }
    float m = 0.f;
    for (int i = blockIdx.x * blockDim.x + threadIdx.x; i < n;
         i += gridDim.x * blockDim.x)
        m = fmaxf(m, fabsf(w[i]));
#pragma unroll
    for (int o = 16; o; o >>= 1)
        m = fmaxf(m, __shfl_xor_sync(0xffffffffu, m, o));
    __shared__ float sm[8];
    int wid = threadIdx.x >> 5;
    if ((threadIdx.x & 31) == 0) sm[wid] = m;
    __syncthreads();
    if (threadIdx.x == 0) {
        for (int i = 1; i < 8; i++) m = fmaxf(m, sm[i]);
        atomicMax(&g_amax[slot], __float_as_uint(m));
    }
}

// wq/wk/wv -> integer codes [k|k] into g_wqkvs rows 0/1024/2048;
// wo/wup/wdn -> integer codes [k|k]; su/sv -> fp32 dequant.
__global__ void k_quant_all(const float* wq, const float* wk, const float* wv,
                            const float* wo, const float* su, const float* sv,
                            const float* wup, const float* wdn) {
    int slot = blockIdx.y;
    const float* src;
    float* fdst = nullptr;
    __nv_bfloat16* idst = nullptr;
    int n, K = 0;
    switch (slot) {
        case 0: src = wq; idst = g_wqkvs; n = D_*D_; K = D_; break;
        case 1: src = wk; idst = g_wqkvs + (size_t)1024 * 2048; n = D_*D_; K = D_; break;
        case 2: src = wv; idst = g_wqkvs + (size_t)2048 * 2048; n = D_*D_; K = D_; break;
        case 3: src = wo; idst = g_wos; n = D_*D_; K = D_; break;
        case 4: src = su; fdst = g_suq; n = S_*S_; break;
        case 5: src = sv; fdst = g_svq; n = S_*S_; break;
        case 6: src = wup; idst = g_wups; n = HID_*D_; K = D_; break;
        default: src = wdn; idst = g_wdns; n = D_*HID_; K = HID_; break;
    }
    float s = __uint_as_float(g_amax[slot]) / 31.0f + 1e-8f;
    for (int i = blockIdx.x * blockDim.x + threadIdx.x; i < n;
         i += gridDim.x * blockDim.x) {
        float q = rintf(src[i] / s);
        q = fminf(fmaxf(q, -31.f), 31.f);
        if (fdst) {
            fdst[i] = q * s;
        } else {
            int r = i / K, c = i - r * K;
            __nv_bfloat16 kq = __float2bfloat16(q);   // exact: |q|<=31
            idst[(size_t)r * 2 * K + c] = kq;
            idst[(size_t)r * 2 * K + K + c] = kq;
        }
    }
}

// ---------------- stalk product: Mt[n][k] = sum_a sv_q[a][n] * su_q[a][k] ----
__global__ void k_stalkM() {
    int idx = blockIdx.x * 256 + threadIdx.x;   // 0..4095
    int n = idx >> 6, k = idx & 63;
    float acc = 0.f;
#pragma unroll 8
    for (int a = 0; a < 64; a++)
        acc += g_svq[a * 64 + n] * g_suq[a * 64 + k];
    __nv_bfloat16 hi = __float2bfloat16(acc);
    g_Mt[idx] = hi;
    g_Mt[4096 + idx] = __float2bfloat16(acc - __bfloat162float(hi));
}

// ---------------- layernorm (+silu) fused with A-side split -----------------
__global__ void k_ln(const float* __restrict__ x, const float* __restrict__ g,
                     const float* __restrict__ bb, __nv_bfloat16* __restrict__ out,
                     int n, int do_silu) {
    extern __shared__ float row[];
    int r = blockIdx.x;
    int tid = threadIdx.x;
    const float* xr = x + (size_t)r * n;
    float s = 0.f, s2 = 0.f;
    for (int i = tid; i < n; i += blockDim.x) {
        float v = xr[i];
        row[i] = v;
        s += v;
        s2 += v * v;
    }
#pragma unroll
    for (int o = 16; o; o >>= 1) {
        s += __shfl_xor_sync(0xffffffffu, s, o);
        s2 += __shfl_xor_sync(0xffffffffu, s2, o);
    }
    __shared__ float rs[8], rs2[8];
    __shared__ float mu_s, inv_s;
    int wid = tid >> 5;
    if ((tid & 31) == 0) { rs[wid] = s; rs2[wid] = s2; }
    __syncthreads();
    if (tid == 0) {
        float S = 0.f, S2 = 0.f;
        int nw = blockDim.x >> 5;
        for (int i = 0; i < nw; i++) { S += rs[i]; S2 += rs2[i]; }
        float mu = S / n;
        float var = S2 / n - mu * mu;
        mu_s = mu;
        inv_s = rsqrtf(var + 1e-5f);
    }
    __syncthreads();
    float mu = mu_s, inv = inv_s;
    __nv_bfloat16* orow = out + (size_t)r * 2 * n;
    for (int i = tid; i < n; i += blockDim.x) {
        float y = (row[i] - mu) * inv * g[i] + bb[i];
        if (do_silu) y = y / (1.0f + __expf(-y));
        __nv_bfloat16 hi = __float2bfloat16(y);
        __nv_bfloat16 lo = __float2bfloat16(y - __bfloat162float(hi));
        orow[i] = hi;
        orow[n + i] = lo;
    }
}

// ---------------- HMMA GEMM ---------------------------------------------------
// mode 0 plain / 1 +residual / 2 SO(2) / 3 bf16 hi-lo 6-plane QKV writer
#define STG 4
#define STG_BYTES 16384

__global__ __launch_bounds__(256, 2)
void k_mma_gemm(const __nv_bfloat16* __restrict__ A,
                const __nv_bfloat16* __restrict__ Bm,
                float* __restrict__ C, const float* __restrict__ R,
                const float* __restrict__ theta, int KK, int N, int mode,
                int slot) {
    extern __shared__ __align__(128) char smraw[];
    uint32_t smb = smem_u32(smraw);
    int tid = threadIdx.x;
    int wid = tid >> 5, lane = tid & 31;
    int wm = wid >> 2, wn = wid & 3;
    int m0 = wm * 64, n0 = wn * 32;
    int bm = blockIdx.y * 128;
    int bn = blockIdx.x * 128;

    float acc[16][4];
#pragma unroll
    for (int i = 0; i < 16; i++)
#pragma unroll
        for (int j = 0; j < 4; j++) acc[i][j] = 0.f;

    const int NC = KK >> 5;
    int r0a = tid >> 2;
    int c0a = tid & 3;
#pragma unroll
    for (int s = 0; s < STG - 1; s++) {
        uint32_t ab = smb + s * STG_BYTES;
        int kof = s << 5;
#pragma unroll
        for (int half = 0; half < 2; half++) {
            int r = r0a + half * 64;
            cpa16(ab + SWZB(r, c0a), A + (size_t)(bm + r) * KK + kof + c0a * 8);
            cpa16(ab + 8192 + SWZB(r, c0a),
                  Bm + (size_t)(bn + r) * KK + kof + c0a * 8);
        }
        CP_COMMIT();
    }

    for (int kc = 0; kc < NC; kc++) {
        CP_WAIT(STG - 2);
        __syncthreads();
        int nk = kc + STG - 1;
        if (nk < NC) {
            uint32_t ab = smb + (nk % STG) * STG_BYTES;
            int kof = nk << 5;
#pragma unroll
            for (int half = 0; half < 2; half++) {
                int r = r0a + half * 64;
                cpa16(ab + SWZB(r, c0a),
                      A + (size_t)(bm + r) * KK + kof + c0a * 8);
                cpa16(ab + 8192 + SWZB(r, c0a),
                      Bm + (size_t)(bn + r) * KK + kof + c0a * 8);
            }
        }
        CP_COMMIT();

        uint32_t ab = smb + (kc % STG) * STG_BYTES;
        uint32_t bb = ab + 8192;
#pragma unroll
        for (int ks = 0; ks < 2; ks++) {
            uint32_t af[4][4];
            int arow = m0 + (lane & 15);
            int ac = ks * 2 + (lane >> 4);
#pragma unroll
            for (int mt = 0; mt < 4; mt++)
                ldm4(af[mt], ab + SWZB(arow + mt * 16, ac));
            uint32_t bf[2][4];
            int brow = n0 + ((lane >> 4) << 3) + (lane & 7);
            int bc = ks * 2 + ((lane >> 3) & 1);
#pragma unroll
            for (int nt2 = 0; nt2 < 2; nt2++)
                ldm4(bf[nt2], bb + SWZB(brow + nt2 * 16, bc));
#pragma unroll
            for (int mt = 0; mt < 4; mt++)
#pragma unroll
                for (int nt = 0; nt < 4; nt++)
                    mma16816(acc[mt * 4 + nt], af[mt],
                             bf[nt >> 1][(nt & 1) * 2],
                             bf[nt >> 1][(nt & 1) * 2 + 1]);
        }
    }

    float scl = 1.0f;
    if (slot >= 0)
        scl = __uint_as_float(g_amax[slot]) / 31.0f + 1e-8f;
    float s3[3] = {scl, scl, scl};
    if (mode == 3) {
#pragma unroll
        for (int s = 0; s < 3; s++)
            s3[s] = __uint_as_float(g_amax[s]) / 31.0f + 1e-8f;
    }
    int lg = lane >> 2, lt = lane & 3;
#pragma unroll
    for (int mt = 0; mt < 4; mt++) {
#pragma unroll
        for (int nt = 0; nt < 4; nt++) {
            float* cf = acc[mt * 4 + nt];
            int row0 = bm + m0 + mt * 16 + lg;
            int col = bn + n0 + nt * 8 + lt * 2;
            float sc2 = (mode == 3) ? s3[col >> 10] : scl;
            float v0 = cf[0] * sc2, v1 = cf[1] * sc2;
            float v2 = cf[2] * sc2, v3 = cf[3] * sc2;
            if (mode == 3) {
                __nv_bfloat16* P = (__nv_bfloat16*)C;
                int seg = col >> 10, c = col & 1023;
                size_t PL = (size_t)4096 * 1024;
                uint32_t h01, l01, h23, l23;
                packhl(h01, l01, v0, v1);
                packhl(h23, l23, v2, v3);
                size_t o0 = (size_t)row0 * 1024 + c;
                size_t o1 = (size_t)(row0 + 8) * 1024 + c;
                *(uint32_t*)(P + 2 * seg * PL + o0) = h01;
                *(uint32_t*)(P + (2 * seg + 1) * PL + o0) = l01;
                *(uint32_t*)(P + 2 * seg * PL + o1) = h23;
                *(uint32_t*)(P + (2 * seg + 1) * PL + o1) = l23;
                continue;
            }
            if (mode == 2) {
                float cs, sn;
                __sincosf(theta[col >> 1], &sn, &cs);
                float a0 = v0, b0 = v1, a1 = v2, b1 = v3;
                v0 = cs * a0 - sn * b0;
                v1 = sn * a0 + cs * b0;
                v2 = cs * a1 - sn * b1;
                v3 = sn * a1 + cs * b1;
            }
            if (mode == 1) {
                float2 r0 = *(const float2*)(R + (size_t)row0 * N + col);
                float2 r1 = *(const float2*)(R + (size_t)(row0 + 8) * N + col);
                v0 += r0.x; v1 += r0.y; v2 += r1.x; v3 += r1.y;
            }
            *(float2*)(C + (size_t)row0 * N + col) = make_float2(v0, v1);
            *(float2*)(C + (size_t)(row0 + 8) * N + col) = make_float2(v2, v3);
        }
    }
}

// ---------------- tensor-core flash attention --------------------------------
// smem: Qh 0 | Ql 16K | Mth 32K | Mtl 40K | KV stage s at 48K+s*32K | bias 112K
#define ATTN_SMEM4 (114688 + 4096)

__global__ __launch_bounds__(256, 1)
void k_attn_tc(const __nv_bfloat16* __restrict__ QS,
               __nv_bfloat16* __restrict__ Osplit,
               const float* __restrict__ ps_ptr) {
    extern __shared__ __align__(16) char sm[];
    uint32_t smb = smem_u32(sm);
    float* bias = (float*)(sm + 114688);
    int Qt = blockIdx.x, h = blockIdx.y, b = blockIdx.z;
    int tid = threadIdx.x, wid = tid >> 5, lane = tid & 31;
    int lg = lane >> 2, lt = lane & 3;
    float ps = ps_ptr[0];
    for (int i = tid; i < 1024; i += 256)
        bias[i] = (i == 0) ? ps
                 : ps * fminf((float)(__ffs(i) - 1), 16.f) * 0.0625f;

    const size_t PL = (size_t)4096 * 1024;
    size_t rowbase = (size_t)b * 1024;
    int colb = h * 64;
    int q0 = Qt * 128;

    // prologue: Q planes + Mt planes + KV tile 0 (single commit group)
    for (int e = tid; e < 2048; e += 256) {
        int pl = e >> 10;
        int r = (e >> 3) & 127, cw = e & 7;
        cpa16(smb + pl * 16384 + SWZ128(r, cw),
              QS + pl * PL + (rowbase + q0 + r) * 1024 + colb + cw * 8);
    }
    for (int e = tid; e < 1024; e += 256) {
        int pl = e >> 9;
        int r = (e >> 3) & 63, cw = e & 7;
        cpa16(smb + 32768 + pl * 8192 + SWZ128(r, cw),
              g_Mt + pl * 4096 + r * 64 + cw * 8);
    }
    for (int e = tid; e < 2048; e += 256) {
        int sub = e >> 9;
        int r = (e >> 3) & 63, cw = e & 7;
        cpa16(smb + 49152 + sub * 8192 + SWZ128(r, cw),
              QS + (2 + sub) * PL + (rowbase + r) * 1024 + colb + cw * 8);
    }
    CP_COMMIT();

    uint32_t aqh[4][4], aql[4][4];
    float m_i[2] = {-1e30f, -1e30f}, l_i[2] = {0.f, 0.f};
    float oac[8][4];
#pragma unroll
    for (int i = 0; i < 8; i++)
#pragma unroll
        for (int j = 0; j < 4; j++) oac[i][j] = 0.f;

    int wq0 = q0 + wid * 16;
    int ntiles = (Qt + 1) * 2;

    for (int jt = 0; jt < ntiles; jt++) {
        if (jt + 1 < ntiles) {
            int k0n = (jt + 1) * 64;
            uint32_t stb = smb + 49152 + ((jt + 1) & 1) * 32768;
            for (int e = tid; e < 2048; e += 256) {
                int sub = e >> 9;
                int r = (e >> 3) & 63, cw = e & 7;
                cpa16(stb + sub * 8192 + SWZ128(r, cw),
                      QS + (2 + sub) * PL + (rowbase + k0n + r) * 1024 + colb + cw * 8);
            }
            CP_COMMIT();
            CP_WAIT(1);
        } else {
            CP_WAIT(0);
        }
        __syncthreads();
        if (jt == 0) {
            // Q' = Q @ M   (3-term), then repack C-frags as A-frags hi/lo
            uint32_t ah[4][4], al[4][4];
            int arow = wid * 16 + (lane & 15);
            int khalf = lane >> 4;
#pragma unroll
            for (int kc = 0; kc < 4; kc++) {
                uint32_t ad = SWZ128(arow, kc * 2 + khalf);
                ldm4(ah[kc], smb + ad);
                ldm4(al[kc], smb + 16384 + ad);
            }
            float cq[8][4];
#pragma unroll
            for (int i = 0; i < 8; i++)
#pragma unroll
                for (int j = 0; j < 4; j++) cq[i][j] = 0.f;
            int brow = ((lane >> 4) << 3) + (lane & 7);
            int bhalf = (lane >> 3) & 1;
#pragma unroll
            for (int kc = 0; kc < 4; kc++) {
#pragma unroll
                for (int nf2 = 0; nf2 < 4; nf2++) {
                    uint32_t bh[4], bl[4];
                    uint32_t ad = SWZ128(nf2 * 16 + brow, kc * 2 + bhalf);
                    ldm4(bh, smb + 32768 + ad);
                    ldm4(bl, smb + 40960 + ad);
                    mma16816(cq[nf2 * 2], ah[kc], bh[0], bh[1]);
                    mma16816(cq[nf2 * 2], ah[kc], bl[0], bl[1]);
                    mma16816(cq[nf2 * 2], al[kc], bh[0], bh[1]);
                    mma16816(cq[nf2 * 2 + 1], ah[kc], bh[2], bh[3]);
                    mma16816(cq[nf2 * 2 + 1], ah[kc], bl[2], bl[3]);
                    mma16816(cq[nf2 * 2 + 1], al[kc], bh[2], bh[3]);
                }
            }
#pragma unroll
            for (int kc = 0; kc < 4; kc++) {
                packhl(aqh[kc][0], aql[kc][0], cq[2 * kc][0], cq[2 * kc][1]);
                packhl(aqh[kc][1], aql[kc][1], cq[2 * kc][2], cq[2 * kc][3]);
                packhl(aqh[kc][2], aql[kc][2], cq[2 * kc + 1][0], cq[2 * kc + 1][1]);
                packhl(aqh[kc][3], aql[kc][3], cq[2 * kc + 1][2], cq[2 * kc + 1][3]);
            }
        }
        int k0 = jt * 64;
        uint32_t stb = smb + 49152 + (jt & 1) * 32768;
        if (k0 <= wq0 + 15) {
            float sc[8][4];
#pragma unroll
            for (int i = 0; i < 8; i++)
#pragma unroll
                for (int j = 0; j < 4; j++) sc[i][j] = 0.f;
            {
                int brow = ((lane >> 4) << 3) + (lane & 7);
                int bhalf = (lane >> 3) & 1;
#pragma unroll
                for (int kc = 0; kc < 4; kc++) {
#pragma unroll
                    for (int nf2 = 0; nf2 < 4; nf2++) {
                        uint32_t bh[4], bl[4];
                        uint32_t ad = SWZ128(nf2 * 16 + brow, kc * 2 + bhalf);
                        ldm4(bh, stb + ad);
                        ldm4(bl, stb + 8192 + ad);
                        mma16816(sc[nf2 * 2], aqh[kc], bh[0], bh[1]);
                        mma16816(sc[nf2 * 2], aqh[kc], bl[0], bl[1]);
                        mma16816(sc[nf2 * 2], aql[kc], bh[0], bh[1]);
                        mma16816(sc[nf2 * 2 + 1], aqh[kc], bh[2], bh[3]);
                        mma16816(sc[nf2 * 2 + 1], aqh[kc], bl[2], bl[3]);
                        mma16816(sc[nf2 * 2 + 1], aql[kc], bh[2], bh[3]);
                    }
                }
            }
            int r0t = wq0 + lg, r1t = r0t + 8;
            bool diag = (k0 + 63 > wq0);
#pragma unroll
            for (int nf = 0; nf < 8; nf++) {
                int c0 = k0 + nf * 8 + 2 * lt;
                int d00 = r0t - c0, d01 = d00 - 1;
                int d10 = r1t - c0, d11 = d10 - 1;
                if (diag) {
                    sc[nf][0] = (d00 < 0) ? -1e30f : sc[nf][0] * 0.125f + bias[d00];
                    sc[nf][1] = (d01 < 0) ? -1e30f : sc[nf][1] * 0.125f + bias[d01];
                    sc[nf][2] = (d10 < 0) ? -1e30f : sc[nf][2] * 0.125f + bias[d10];
                    sc[nf][3] = (d11 < 0) ? -1e30f : sc[nf][3] * 0.125f + bias[d11];
                } else {
                    sc[nf][0] = sc[nf][0] * 0.125f + bias[d00];
                    sc[nf][1] = sc[nf][1] * 0.125f + bias[d01];
                    sc[nf][2] = sc[nf][2] * 0.125f + bias[d10];
                    sc[nf][3] = sc[nf][3] * 0.125f + bias[d11];
                }
            }
#pragma unroll
            for (int rh = 0; rh < 2; rh++) {
                float rm = -1e30f;
#pragma unroll
                for (int nf = 0; nf < 8; nf++)
                    rm = fmaxf(rm, fmaxf(sc[nf][rh * 2], sc[nf][rh * 2 + 1]));
                rm = fmaxf(rm, __shfl_xor_sync(0xffffffffu, rm, 1));
                rm = fmaxf(rm, __shfl_xor_sync(0xffffffffu, rm, 2));
                float mnew = fmaxf(m_i[rh], rm);
                float alpha = __expf(m_i[rh] - mnew);
                m_i[rh] = mnew;
                float rsum = 0.f;
#pragma unroll
                for (int nf = 0; nf < 8; nf++) {
                    float p0 = __expf(sc[nf][rh * 2] - mnew);
                    float p1 = __expf(sc[nf][rh * 2 + 1] - mnew);
                    sc[nf][rh * 2] = p0;
                    sc[nf][rh * 2 + 1] = p1;
                    rsum += p0 + p1;
                }
                rsum += __shfl_xor_sync(0xffffffffu, rsum, 1);
                rsum += __shfl_xor_sync(0xffffffffu, rsum, 2);
                l_i[rh] = l_i[rh] * alpha + rsum;
#pragma unroll
                for (int nf = 0; nf < 8; nf++) {
                    oac[nf][rh * 2] *= alpha;
                    oac[nf][rh * 2 + 1] *= alpha;
                }
            }
            {
                int vrow = (lane & 7) + (((lane >> 3) & 1) << 3);
                int vhalf = (lane >> 4) & 1;
#pragma unroll
                for (int uk = 0; uk < 4; uk++) {
                    uint32_t ph[4], pl[4];
                    packhl(ph[0], pl[0], sc[2 * uk][0], sc[2 * uk][1]);
                    packhl(ph[1], pl[1], sc[2 * uk][2], sc[2 * uk][3]);
                    packhl(ph[2], pl[2], sc[2 * uk + 1][0], sc[2 * uk + 1][1]);
                    packhl(ph[3], pl[3], sc[2 * uk + 1][2], sc[2 * uk + 1][3]);
#pragma unroll
                    for (int sf2 = 0; sf2 < 4; sf2++) {
                        uint32_t vh[4], vl[4];
                        uint32_t ad = SWZ128(uk * 16 + vrow, sf2 * 2 + vhalf);
                        ldm4t(vh, stb + 16384 + ad);
                        ldm4t(vl, stb + 24576 + ad);
                        mma16816(oac[sf2 * 2], ph, vh[0], vh[1]);
                        mma16816(oac[sf2 * 2], ph, vl[0], vl[1]);
                        mma16816(oac[sf2 * 2], pl, vh[0], vh[1]);
                        mma16816(oac[sf2 * 2 + 1], ph, vh[2], vh[3]);
                        mma16816(oac[sf2 * 2 + 1], ph, vl[2], vl[3]);
                        mma16816(oac[sf2 * 2 + 1], pl, vh[2], vh[3]);
                    }
                }
            }
        }
        __syncthreads();
    }
#pragma unroll
    for (int rh = 0; rh < 2; rh++) {
        float inv = 1.f / l_i[rh];
        size_t orow = (rowbase + wq0 + lg + rh * 8) * 2048;
#pragma unroll
        for (int nf = 0; nf < 8; nf++) {
            float v0 = oac[nf][rh * 2] * inv;
            float v1 = oac[nf][rh * 2 + 1] * inv;
            uint32_t hp, lp;
            packhl(hp, lp, v0, v1);
            int col = h * 64 + nf * 8 + 2 * lt;
            *(uint32_t*)(Osplit + orow + col) = hp;
            *(uint32_t*)(Osplit + orow + 1024 + col) = lp;
        }
    }
}

// ---------------- host orchestration ----------------------------------------
extern "C" void kernel_launch(void* const* d_in, const int* in_sizes, int n_in,
                              void* d_out, int out_size) {
    const float* x      = (const float*)d_in[0];
    const float* wq     = (const float*)d_in[1];
    const float* wk     = (const float*)d_in[2];
    const float* wv     = (const float*)d_in[3];
    const float* wo     = (const float*)d_in[4];
    const float* su     = (const float*)d_in[5];
    const float* sv     = (const float*)d_in[6];
    const float* pscale = (const float*)d_in[7];
    const float* n1g    = (const float*)d_in[8];
    const float* n1b    = (const float*)d_in[9];
    const float* n2g    = (const float*)d_in[10];
    const float* n2b    = (const float*)d_in[11];
    const float* w_up   = (const float*)d_in[12];
    const float* w_down = (const float*)d_in[13];
    const float* theta  = (const float*)d_in[14];
    const float* mg     = (const float*)d_in[15];
    const float* mb     = (const float*)d_in[16];
    float* out = (float*)d_out;

    float *qkv, *x1, *hb;
    __nv_bfloat16 *as_, *acts, *wqkvs, *wos, *wups, *wdns;
    cudaGetSymbolAddress((void**)&qkv, g_qkv);
    cudaGetSymbolAddress((void**)&x1, g_x1);
    cudaGetSymbolAddress((void**)&hb, g_h);
    cudaGetSymbolAddress((void**)&as_, g_as);
    cudaGetSymbolAddress((void**)&acts, g_acts);
    cudaGetSymbolAddress((void**)&wqkvs, g_wqkvs);
    cudaGetSymbolAddress((void**)&wos, g_wos);
    cudaGetSymbolAddress((void**)&wups, g_wups);
    cudaGetSymbolAddress((void**)&wdns, g_wdns);

    const int GSM = STG * STG_BYTES;
    cudaFuncSetAttribute(k_attn_tc, cudaFuncAttributeMaxDynamicSharedMemorySize,
                         ATTN_SMEM4);
    cudaFuncSetAttribute(k_mma_gemm,
                         cudaFuncAttributeMaxDynamicSharedMemorySize, GSM);

    k_zero_amax<<<1, 32>>>();
    k_absmax_all<<<dim3(256, 8), 256>>>(wq, wk, wv, wo, su, sv, w_up, w_down);
    k_quant_all<<<dim3(1024, 8), 256>>>(wq, wk, wv, wo, su, sv, w_up, w_down);
    k_stalkM<<<16, 256>>>();
    k_ln<<<BT_, 256, D_ * 4>>>(x, n1g, n1b, as_, D_, 0);
    k_mma_gemm<<<dim3(24, 32), 256, GSM>>>(as_, wqkvs, qkv, nullptr, nullptr,
                                           2 * D_, 3 * D_, 3, -1);
    k_attn_tc<<<dim3(8, 16, 4), 256, ATTN_SMEM4>>>(
        (const __nv_bfloat16*)qkv, as_, pscale);
    k_mma_gemm<<<dim3(8, 32), 256, GSM>>>(as_, wos, x1, x, nullptr,
                                          2 * D_, D_, 1, 3);
    k_ln<<<BT_, 256, D_ * 4>>>(x1, n2g, n2b, as_, D_, 0);
    k_mma_gemm<<<dim3(24, 32), 256, GSM>>>(as_, wups, hb, nullptr, theta,
                                           2 * D_, HID_, 2, 6);
    k_ln<<<BT_, 256, HID_ * 4>>>(hb, mg, mb, acts, HID_, 1);
    k_mma_gemm<<<dim3(8, 32), 256, GSM>>>(acts, wdns, out, x1, nullptr,
                                          2 * HID_, D_, 1, 7);
}